// round 5
// baseline (speedup 1.0000x reference)
#include <cuda_runtime.h>
#include <math.h>

#define B_  2
#define L_  2048
#define D_  2048
#define H_  16
#define HD_ 128

// Scratch (static __device__ — no runtime allocation)
__device__ float g_q[(size_t)B_ * H_ * L_ * HD_];
__device__ float g_k[(size_t)B_ * H_ * L_ * HD_];
__device__ float g_v[(size_t)B_ * H_ * L_ * HD_];
__device__ float g_c[(size_t)B_ * L_ * H_ * HD_];

__device__ __forceinline__ unsigned f2tf32(float f) {
    unsigned u;
    asm("cvt.rna.tf32.f32 %0, %1;" : "=r"(u) : "f"(f));
    return u;
}

__device__ __forceinline__ void mma_tf32(float* c, const unsigned* a,
                                         unsigned b0, unsigned b1) {
    asm volatile(
        "mma.sync.aligned.m16n8k8.row.col.f32.tf32.tf32.f32 "
        "{%0,%1,%2,%3},{%4,%5,%6,%7},{%8,%9},{%0,%1,%2,%3};\n"
        : "+f"(c[0]), "+f"(c[1]), "+f"(c[2]), "+f"(c[3])
        : "r"(a[0]), "r"(a[1]), "r"(a[2]), "r"(a[3]), "r"(b0), "r"(b1));
}

__device__ __forceinline__ void cp16(void* smp, const void* g) {
    unsigned s = (unsigned)__cvta_generic_to_shared(smp);
    asm volatile("cp.async.cg.shared.global [%0], [%1], 16;" :: "r"(s), "l"(g));
}

// ---------------------------------------------------------------------------
// TF32 tensor-core GEMM v2: cp.async 3-stage pipeline, BK=16, 2 CTAs/SM.
// C = A(MxK) @ B(KxN), row-major. 128x128 block, 8 warps of 64x32.
// smem fp32 (cvt to tf32 at fragment load). Conflict-free pitches:
//   A [m][k] pitch 20  (banks qr*20+qc distinct)
//   B [k][n] pitch 136 (banks qc*8+qr distinct)
// MODE 0: scatter epilogue to (B,H,L,hd). MODE 1: plain row-major.
// ---------------------------------------------------------------------------
#define A_LD 20
#define B_LD 136
#define STAGE_A (128 * A_LD)          // 2560 words
#define STAGE_B (16 * B_LD)           // 2176 words
#define STAGE_W (STAGE_A + STAGE_B)   // 4736 words
#define GEMM_SMEM (3 * STAGE_W * 4)   // 56832 bytes

template <int MODE>
__global__ __launch_bounds__(256, 2) void gemm_tf32(
    const float* __restrict__ A, const float* __restrict__ Bm,
    float* __restrict__ C, int M, int N, int K)
{
    extern __shared__ float sm[];

    const int tid  = threadIdx.x;
    const int warp = tid >> 5, lane = tid & 31;
    const int qr = lane >> 2, qc = lane & 3;
    const int wm = (warp & 1) * 64;
    const int wn = (warp >> 1) * 32;
    const int bm = blockIdx.y * 128, bn = blockIdx.x * 128;

    // cp.async coords (2 x 16B per thread for each of A and B per stage)
    const int ia0 = tid * 2, ia1 = tid * 2 + 1;
    const int rA0 = ia0 >> 2, cA0 = (ia0 & 3) * 4;
    const int rA1 = ia1 >> 2, cA1 = (ia1 & 3) * 4;
    const int rB0 = ia0 >> 5, cB0 = (ia0 & 31) * 4;
    const int rB1 = ia1 >> 5, cB1 = (ia1 & 31) * 4;

    float acc[4][4][4];
#pragma unroll
    for (int mt = 0; mt < 4; mt++)
#pragma unroll
        for (int nt = 0; nt < 4; nt++)
#pragma unroll
            for (int u = 0; u < 4; u++) acc[mt][nt][u] = 0.f;

    const int NCHUNK = K >> 4;   // K/16

    // issue helper (stage s, k-offset k0)
    auto issue = [&](int s, int k0) {
        float* As = sm + s * STAGE_W;
        float* Bs = As + STAGE_A;
        cp16(&As[rA0 * A_LD + cA0], A + (size_t)(bm + rA0) * K + k0 + cA0);
        cp16(&As[rA1 * A_LD + cA1], A + (size_t)(bm + rA1) * K + k0 + cA1);
        cp16(&Bs[rB0 * B_LD + cB0], Bm + (size_t)(k0 + rB0) * N + bn + cB0);
        cp16(&Bs[rB1 * B_LD + cB1], Bm + (size_t)(k0 + rB1) * N + bn + cB1);
        asm volatile("cp.async.commit_group;");
    };

    issue(0, 0);
    issue(1, 16);

    for (int ch = 0; ch < NCHUNK; ch++) {
        asm volatile("cp.async.wait_group 1;");
        __syncthreads();

        // prefetch stage ch+2 (safe: all warps are past compute of ch-1)
        if (ch + 2 < NCHUNK) {
            int s = ch + 2;
            issue(s - (s / 3) * 3, s * 16);
        } else {
            asm volatile("cp.async.commit_group;");
        }

        const float* As = sm + (ch - (ch / 3) * 3) * STAGE_W;
        const float* Bs = As + STAGE_A;

#pragma unroll
        for (int ks = 0; ks < 2; ks++) {
            const int kb = ks * 8;
            unsigned a[4][4], b[4][2];
#pragma unroll
            for (int mt = 0; mt < 4; mt++) {
                int m = wm + mt * 16 + qr;
                a[mt][0] = f2tf32(As[m * A_LD + kb + qc]);
                a[mt][1] = f2tf32(As[(m + 8) * A_LD + kb + qc]);
                a[mt][2] = f2tf32(As[m * A_LD + kb + qc + 4]);
                a[mt][3] = f2tf32(As[(m + 8) * A_LD + kb + qc + 4]);
            }
#pragma unroll
            for (int nt = 0; nt < 4; nt++) {
                int n = wn + nt * 8 + qr;
                b[nt][0] = f2tf32(Bs[(kb + qc) * B_LD + n]);
                b[nt][1] = f2tf32(Bs[(kb + qc + 4) * B_LD + n]);
            }
#pragma unroll
            for (int mt = 0; mt < 4; mt++)
#pragma unroll
                for (int nt = 0; nt < 4; nt++)
                    mma_tf32(acc[mt][nt], a[mt], b[nt][0], b[nt][1]);
        }
    }

    // epilogue: c0,c1 at (row, 2qc), c2,c3 at (row+8, 2qc)
#pragma unroll
    for (int mt = 0; mt < 4; mt++) {
#pragma unroll
        for (int nt = 0; nt < 4; nt++) {
            int row = bm + wm + mt * 16 + qr;
            int col = bn + wn + nt * 8 + 2 * qc;
            float2 r0 = make_float2(acc[mt][nt][0], acc[mt][nt][1]);
            float2 r1 = make_float2(acc[mt][nt][2], acc[mt][nt][3]);
            if (MODE == 0) {
                int b0 = row >> 11, l0 = row & (L_ - 1);
                int h = col >> 7, d = col & (HD_ - 1);
                *(float2*)(C + ((((size_t)b0 * H_ + h) * L_ + l0) * HD_ + d)) = r0;
                int row1 = row + 8;
                int b1 = row1 >> 11, l1 = row1 & (L_ - 1);
                *(float2*)(C + ((((size_t)b1 * H_ + h) * L_ + l1) * HD_ + d)) = r1;
            } else {
                *(float2*)(C + (size_t)row * N + col) = r0;
                *(float2*)(C + (size_t)(row + 8) * N + col) = r1;
            }
        }
    }
}

// ---------------------------------------------------------------------------
// RoPE in-place on q and k.
// ---------------------------------------------------------------------------
__global__ void rope_kernel(float* __restrict__ qb, float* __restrict__ kb)
{
    int idx = blockIdx.x * blockDim.x + threadIdx.x;
    if (idx >= B_ * H_ * L_ * 64) return;
    int j  = idx & 63;
    int l  = (idx >> 6) & (L_ - 1);
    int bh = idx >> 17;

    float freq = expf(-9.210340371976184f * (float)j * (1.0f / 64.0f));
    float ang = (float)l * freq;
    float s, c;
    sincosf(ang, &s, &c);

    size_t base = ((size_t)bh * L_ + l) * HD_ + j;
    float q1 = qb[base], q2 = qb[base + 64];
    qb[base]      = q1 * c - q2 * s;
    qb[base + 64] = q1 * s + q2 * c;
    float k1 = kb[base], k2 = kb[base + 64];
    kb[base]      = k1 * c - k2 * s;
    kb[base + 64] = k1 * s + k2 * c;
}

// ---------------------------------------------------------------------------
// Tensor-core attention + memory path (unchanged from round 4 — verified).
// ---------------------------------------------------------------------------
#define QS_OFF 0
#define KS_OFF 16896
#define VS_OFF 25344
#define PS_OFF 34048
#define MS_OFF 16896
#define NS_OFF 34304
#define LDQ 132
#define LDK 132
#define LDV 136
#define LDP 68
#define LDM 136
#define ATTN_SMEM (42752 * 4)

__global__ __launch_bounds__(256, 1) void attn_tc(
    const float* __restrict__ qb, const float* __restrict__ kb,
    const float* __restrict__ vb, const float* __restrict__ gatep,
    const float* __restrict__ memp, const float* __restrict__ normp,
    float* __restrict__ cb)
{
    extern __shared__ float smf[];
    unsigned* smu = (unsigned*)smf;

    const int tid = threadIdx.x;
    const int w = tid >> 5, lane = tid & 31;
    const int qr = lane >> 2, qc = lane & 3;
    const int qt = blockIdx.x;
    const int bh = blockIdx.y;
    const int h  = bh & (H_ - 1);
    const int b  = bh >> 4;
    const int m0 = w * 16 + qr;

    const float* qblk  = qb + ((size_t)bh * L_ + qt * 128) * HD_;
    const float* kbase = kb + (size_t)bh * L_ * HD_;
    const float* vbase = vb + (size_t)bh * L_ * HD_;

#pragma unroll
    for (int it = 0; it < 16; it++) {
        int row = w + 8 * it;
        float4 v = *(const float4*)(qblk + (size_t)row * HD_ + lane * 4);
        *(uint4*)&smu[QS_OFF + row * LDQ + lane * 4] =
            make_uint4(f2tf32(v.x), f2tf32(v.y), f2tf32(v.z), f2tf32(v.w));
    }

    float o[16][4];
#pragma unroll
    for (int nt = 0; nt < 16; nt++)
#pragma unroll
        for (int u = 0; u < 4; u++) o[nt][u] = 0.f;
    float mrow0 = -1e30f, mrow1 = -1e30f;
    float lrow0 = 0.f, lrow1 = 0.f;

    const float scale = 0.08838834764831845f;

    for (int kt = 0; kt < 32; kt++) {
        const float* kblk = kbase + (size_t)kt * 64 * HD_;
        const float* vblk = vbase + (size_t)kt * 64 * HD_;
#pragma unroll
        for (int it = 0; it < 8; it++) {
            int row = w + 8 * it;
            float4 kv = *(const float4*)(kblk + (size_t)row * HD_ + lane * 4);
            *(uint4*)&smu[KS_OFF + row * LDK + lane * 4] =
                make_uint4(f2tf32(kv.x), f2tf32(kv.y), f2tf32(kv.z), f2tf32(kv.w));
            float4 vv = *(const float4*)(vblk + (size_t)row * HD_ + lane * 4);
            *(uint4*)&smu[VS_OFF + row * LDV + lane * 4] =
                make_uint4(f2tf32(vv.x), f2tf32(vv.y), f2tf32(vv.z), f2tf32(vv.w));
        }
        __syncthreads();

        float sa[8][4];
#pragma unroll
        for (int nt = 0; nt < 8; nt++)
#pragma unroll
            for (int u = 0; u < 4; u++) sa[nt][u] = 0.f;

#pragma unroll
        for (int ks = 0; ks < 16; ks++) {
            const int kb8 = ks * 8;
            unsigned a[4];
            a[0] = smu[QS_OFF + m0 * LDQ + kb8 + qc];
            a[1] = smu[QS_OFF + (m0 + 8) * LDQ + kb8 + qc];
            a[2] = smu[QS_OFF + m0 * LDQ + kb8 + qc + 4];
            a[3] = smu[QS_OFF + (m0 + 8) * LDQ + kb8 + qc + 4];
#pragma unroll
            for (int nt = 0; nt < 8; nt++) {
                int n = nt * 8 + qr;
                unsigned b0 = smu[KS_OFF + n * LDK + kb8 + qc];
                unsigned b1 = smu[KS_OFF + n * LDK + kb8 + qc + 4];
                mma_tf32(sa[nt], a, b0, b1);
            }
        }

        float cand0 = -1e30f, cand1 = -1e30f;
#pragma unroll
        for (int nt = 0; nt < 8; nt++) {
            cand0 = fmaxf(cand0, fmaxf(sa[nt][0], sa[nt][1]));
            cand1 = fmaxf(cand1, fmaxf(sa[nt][2], sa[nt][3]));
        }
        cand0 *= scale; cand1 *= scale;
        cand0 = fmaxf(cand0, __shfl_xor_sync(0xffffffffu, cand0, 1));
        cand0 = fmaxf(cand0, __shfl_xor_sync(0xffffffffu, cand0, 2));
        cand1 = fmaxf(cand1, __shfl_xor_sync(0xffffffffu, cand1, 1));
        cand1 = fmaxf(cand1, __shfl_xor_sync(0xffffffffu, cand1, 2));

        float newm0 = fmaxf(mrow0, cand0), newm1 = fmaxf(mrow1, cand1);
        float corr0 = __expf(mrow0 - newm0), corr1 = __expf(mrow1 - newm1);
        mrow0 = newm0; mrow1 = newm1;

        float psum0 = 0.f, psum1 = 0.f;
#pragma unroll
        for (int nt = 0; nt < 8; nt++) {
            float p0 = __expf(sa[nt][0] * scale - newm0);
            float p1 = __expf(sa[nt][1] * scale - newm0);
            float p2 = __expf(sa[nt][2] * scale - newm1);
            float p3 = __expf(sa[nt][3] * scale - newm1);
            psum0 += p0 + p1; psum1 += p2 + p3;
            float2 lo, hi;
            lo.x = __uint_as_float(f2tf32(p0)); lo.y = __uint_as_float(f2tf32(p1));
            hi.x = __uint_as_float(f2tf32(p2)); hi.y = __uint_as_float(f2tf32(p3));
            *(float2*)&smf[PS_OFF + m0 * LDP + nt * 8 + 2 * qc] = lo;
            *(float2*)&smf[PS_OFF + (m0 + 8) * LDP + nt * 8 + 2 * qc] = hi;
        }
        psum0 += __shfl_xor_sync(0xffffffffu, psum0, 1);
        psum0 += __shfl_xor_sync(0xffffffffu, psum0, 2);
        psum1 += __shfl_xor_sync(0xffffffffu, psum1, 1);
        psum1 += __shfl_xor_sync(0xffffffffu, psum1, 2);
        lrow0 = lrow0 * corr0 + psum0;
        lrow1 = lrow1 * corr1 + psum1;

#pragma unroll
        for (int nt = 0; nt < 16; nt++) {
            o[nt][0] *= corr0; o[nt][1] *= corr0;
            o[nt][2] *= corr1; o[nt][3] *= corr1;
        }
        __syncthreads();

#pragma unroll
        for (int ks = 0; ks < 8; ks++) {
            const int kb8 = ks * 8;
            unsigned a[4];
            a[0] = __float_as_uint(smf[PS_OFF + m0 * LDP + kb8 + qc]);
            a[1] = __float_as_uint(smf[PS_OFF + (m0 + 8) * LDP + kb8 + qc]);
            a[2] = __float_as_uint(smf[PS_OFF + m0 * LDP + kb8 + qc + 4]);
            a[3] = __float_as_uint(smf[PS_OFF + (m0 + 8) * LDP + kb8 + qc + 4]);
#pragma unroll
            for (int nt = 0; nt < 16; nt++) {
                int n = nt * 8 + qr;
                unsigned b0 = smu[VS_OFF + (kb8 + qc) * LDV + n];
                unsigned b1 = smu[VS_OFF + (kb8 + qc + 4) * LDV + n];
                mma_tf32(o[nt], a, b0, b1);
            }
        }
        __syncthreads();
    }

    // ================== epilogue: memory path ==================
    const float* mptr = memp + (size_t)bh * HD_ * HD_;
#pragma unroll
    for (int it = 0; it < 16; it++) {
        int row = w + 8 * it;
        float4 v = *(const float4*)(mptr + (size_t)row * HD_ + lane * 4);
        *(uint4*)&smu[MS_OFF + row * LDM + lane * 4] =
            make_uint4(f2tf32(v.x), f2tf32(v.y), f2tf32(v.z), f2tf32(v.w));
    }
    if (tid < 128) smf[NS_OFF + tid] = normp[(size_t)bh * HD_ + tid];

#pragma unroll
    for (int it = 0; it < 64; it++) {
        int e = tid + it * 256;
        int row = e >> 7, col = e & 127;
        float qv = smf[QS_OFF + row * LDQ + col];
        float qf = qv > 0.f ? qv + 1.f : __expf(qv);
        smu[QS_OFF + row * LDQ + col] = f2tf32(qf);
    }
    __syncthreads();

    float den0 = 0.f, den1 = 0.f;
#pragma unroll 8
    for (int j = 0; j < 32; j++) {
        int d = qc + 4 * j;
        float nv = smf[NS_OFF + d];
        den0 = fmaf(smf[QS_OFF + m0 * LDQ + d], nv, den0);
        den1 = fmaf(smf[QS_OFF + (m0 + 8) * LDQ + d], nv, den1);
    }
    den0 += __shfl_xor_sync(0xffffffffu, den0, 1);
    den0 += __shfl_xor_sync(0xffffffffu, den0, 2);
    den1 += __shfl_xor_sync(0xffffffffu, den1, 1);
    den1 += __shfl_xor_sync(0xffffffffu, den1, 2);

    const float g  = 1.f / (1.f + __expf(-gatep[h]));
    const float og = 1.f - g;
    const float invl0 = og / lrow0, invl1 = og / lrow1;
    const float invd0 = g / den0,   invd1 = g / den1;

    const int l0 = qt * 128 + m0;
    float* dst0 = cb + ((size_t)b * L_ + l0) * (H_ * HD_) + h * HD_;
    float* dst1 = cb + ((size_t)b * L_ + l0 + 8) * (H_ * HD_) + h * HD_;

#pragma unroll
    for (int pass = 0; pass < 2; pass++) {
        float ma[8][4];
#pragma unroll
        for (int nt = 0; nt < 8; nt++)
#pragma unroll
            for (int u = 0; u < 4; u++) ma[nt][u] = 0.f;

#pragma unroll
        for (int ks = 0; ks < 16; ks++) {
            const int kb8 = ks * 8;
            unsigned a[4];
            a[0] = smu[QS_OFF + m0 * LDQ + kb8 + qc];
            a[1] = smu[QS_OFF + (m0 + 8) * LDQ + kb8 + qc];
            a[2] = smu[QS_OFF + m0 * LDQ + kb8 + qc + 4];
            a[3] = smu[QS_OFF + (m0 + 8) * LDQ + kb8 + qc + 4];
#pragma unroll
            for (int nt = 0; nt < 8; nt++) {
                int n = (pass * 8 + nt) * 8 + qr;
                unsigned b0 = smu[MS_OFF + (kb8 + qc) * LDM + n];
                unsigned b1 = smu[MS_OFF + (kb8 + qc + 4) * LDM + n];
                mma_tf32(ma[nt], a, b0, b1);
            }
        }

#pragma unroll
        for (int nt = 0; nt < 8; nt++) {
            int gnt = pass * 8 + nt;
            int col = gnt * 8 + 2 * qc;
            float2 r0, r1;
            r0.x = ma[nt][0] * invd0 + o[gnt][0] * invl0;
            r0.y = ma[nt][1] * invd0 + o[gnt][1] * invl0;
            r1.x = ma[nt][2] * invd1 + o[gnt][2] * invl1;
            r1.y = ma[nt][3] * invd1 + o[gnt][3] * invl1;
            *(float2*)(dst0 + col) = r0;
            *(float2*)(dst1 + col) = r1;
        }
    }
}

// ---------------------------------------------------------------------------

extern "C" void kernel_launch(void* const* d_in, const int* in_sizes, int n_in,
                              void* d_out, int out_size)
{
    const float* x      = (const float*)d_in[0];
    const float* Wq     = (const float*)d_in[1];
    const float* Wk     = (const float*)d_in[2];
    const float* Wv     = (const float*)d_in[3];
    const float* Wo     = (const float*)d_in[4];
    const float* gate   = (const float*)d_in[5];
    const float* memory = (const float*)d_in[6];
    const float* norm   = (const float*)d_in[7];
    float* out = (float*)d_out;

    float *qb, *kb, *vb, *cb;
    cudaGetSymbolAddress((void**)&qb, g_q);
    cudaGetSymbolAddress((void**)&kb, g_k);
    cudaGetSymbolAddress((void**)&vb, g_v);
    cudaGetSymbolAddress((void**)&cb, g_c);

    cudaFuncSetAttribute(gemm_tf32<0>, cudaFuncAttributeMaxDynamicSharedMemorySize, GEMM_SMEM);
    cudaFuncSetAttribute(gemm_tf32<1>, cudaFuncAttributeMaxDynamicSharedMemorySize, GEMM_SMEM);

    dim3 gg(16, 32);   // N/128, M/128
    gemm_tf32<0><<<gg, 256, GEMM_SMEM>>>(x, Wq, qb, B_ * L_, H_ * HD_, D_);
    gemm_tf32<0><<<gg, 256, GEMM_SMEM>>>(x, Wk, kb, B_ * L_, H_ * HD_, D_);
    gemm_tf32<0><<<gg, 256, GEMM_SMEM>>>(x, Wv, vb, B_ * L_, H_ * HD_, D_);

    int nrope = B_ * H_ * L_ * 64;
    rope_kernel<<<nrope / 256, 256>>>(qb, kb);

    cudaFuncSetAttribute(attn_tc, cudaFuncAttributeMaxDynamicSharedMemorySize, ATTN_SMEM);
    attn_tc<<<dim3(16, 32), 256, ATTN_SMEM>>>(qb, kb, vb, gate, memory, norm, cb);

    gemm_tf32<1><<<gg, 256, GEMM_SMEM>>>(cb, Wo, out, B_ * L_, H_ * HD_, D_);
}

// round 6
// speedup vs baseline: 1.0800x; 1.0800x over previous
#include <cuda_runtime.h>
#include <math.h>

#define B_  2
#define L_  2048
#define D_  2048
#define H_  16
#define HD_ 128

// Scratch (static __device__ — no runtime allocation)
__device__ float g_q[(size_t)B_ * H_ * L_ * HD_];
__device__ float g_k[(size_t)B_ * H_ * L_ * HD_];
__device__ float g_v[(size_t)B_ * H_ * L_ * HD_];
__device__ float g_c[(size_t)B_ * L_ * H_ * HD_];

__device__ __forceinline__ unsigned f2tf32(float f) {
    unsigned u;
    asm("cvt.rna.tf32.f32 %0, %1;" : "=r"(u) : "f"(f));
    return u;
}

__device__ __forceinline__ void mma_tf32(float* c, const unsigned* a,
                                         unsigned b0, unsigned b1) {
    asm volatile(
        "mma.sync.aligned.m16n8k8.row.col.f32.tf32.tf32.f32 "
        "{%0,%1,%2,%3},{%4,%5,%6,%7},{%8,%9},{%0,%1,%2,%3};\n"
        : "+f"(c[0]), "+f"(c[1]), "+f"(c[2]), "+f"(c[3])
        : "r"(a[0]), "r"(a[1]), "r"(a[2]), "r"(a[3]), "r"(b0), "r"(b1));
}

// ---------------------------------------------------------------------------
// TF32 tensor-core GEMM (round-4 skeleton, BK=32, register-staged loads,
// double-buffered smem). Fixes vs round 4:
//   BS_LD 132 -> 136  (b-frag LDS: bank = qc*8+qr, all 32 lanes distinct)
//   uint4 STS.128 stage fill
// MODE 0: scatter epilogue to (B,H,L,hd). MODE 1: plain row-major.
// ---------------------------------------------------------------------------
#define AS_LD 36
#define BS_LD 136
#define GEMM_SMEM ((2 * (128 * AS_LD + 32 * BS_LD)) * 4)   // 71680 B

template <int MODE>
__global__ __launch_bounds__(256, 1) void gemm_tf32(
    const float* __restrict__ A, const float* __restrict__ Bm,
    float* __restrict__ C, int M, int N, int K)
{
    extern __shared__ unsigned sm[];
    unsigned* As = sm;
    unsigned* Bs = sm + 2 * 128 * AS_LD;

    const int tid  = threadIdx.x;
    const int warp = tid >> 5, lane = tid & 31;
    const int qr = lane >> 2, qc = lane & 3;
    const int wm = (warp & 1) * 64;
    const int wn = (warp >> 1) * 32;
    const int bm = blockIdx.y * 128, bn = blockIdx.x * 128;

    const int ar = tid >> 3, ac4 = tid & 7;
    const int br = tid >> 5, bc4 = tid & 31;

    float acc[4][4][4];
#pragma unroll
    for (int mt = 0; mt < 4; mt++)
#pragma unroll
        for (int nt = 0; nt < 4; nt++)
#pragma unroll
            for (int u = 0; u < 4; u++) acc[mt][nt][u] = 0.f;

    float4 ra[4], rb[4];

#pragma unroll
    for (int it = 0; it < 4; it++)
        ra[it] = *(const float4*)(A + (size_t)(bm + ar + it * 32) * K + ac4 * 4);
#pragma unroll
    for (int it = 0; it < 4; it++)
        rb[it] = *(const float4*)(Bm + (size_t)(br + it * 8) * N + bn + bc4 * 4);

    int p = 0;
#pragma unroll
    for (int it = 0; it < 4; it++)
        *(uint4*)&As[(ar + it * 32) * AS_LD + ac4 * 4] =
            make_uint4(f2tf32(ra[it].x), f2tf32(ra[it].y),
                       f2tf32(ra[it].z), f2tf32(ra[it].w));
#pragma unroll
    for (int it = 0; it < 4; it++)
        *(uint4*)&Bs[(br + it * 8) * BS_LD + bc4 * 4] =
            make_uint4(f2tf32(rb[it].x), f2tf32(rb[it].y),
                       f2tf32(rb[it].z), f2tf32(rb[it].w));
    __syncthreads();

    const int NCHUNK = K >> 5;
    for (int ch = 0; ch < NCHUNK; ch++) {
        if (ch + 1 < NCHUNK) {
            int k0 = (ch + 1) << 5;
#pragma unroll
            for (int it = 0; it < 4; it++)
                ra[it] = *(const float4*)(A + (size_t)(bm + ar + it * 32) * K + k0 + ac4 * 4);
#pragma unroll
            for (int it = 0; it < 4; it++)
                rb[it] = *(const float4*)(Bm + (size_t)(k0 + br + it * 8) * N + bn + bc4 * 4);
        }

        const unsigned* Ab = As + p * 128 * AS_LD;
        const unsigned* Bb = Bs + p * 32 * BS_LD;

#pragma unroll
        for (int s = 0; s < 4; s++) {
            const int kb = s * 8;
            unsigned a[4][4], b[4][2];
#pragma unroll
            for (int mt = 0; mt < 4; mt++) {
                int m = wm + mt * 16 + qr;
                a[mt][0] = Ab[m * AS_LD + kb + qc];
                a[mt][1] = Ab[(m + 8) * AS_LD + kb + qc];
                a[mt][2] = Ab[m * AS_LD + kb + qc + 4];
                a[mt][3] = Ab[(m + 8) * AS_LD + kb + qc + 4];
            }
#pragma unroll
            for (int nt = 0; nt < 4; nt++) {
                int n = wn + nt * 8 + qr;
                b[nt][0] = Bb[(kb + qc) * BS_LD + n];
                b[nt][1] = Bb[(kb + qc + 4) * BS_LD + n];
            }
#pragma unroll
            for (int mt = 0; mt < 4; mt++)
#pragma unroll
                for (int nt = 0; nt < 4; nt++)
                    mma_tf32(acc[mt][nt], a[mt], b[nt][0], b[nt][1]);
        }

        if (ch + 1 < NCHUNK) {
            int q = p ^ 1;
            unsigned* Aw = As + q * 128 * AS_LD;
            unsigned* Bw = Bs + q * 32 * BS_LD;
#pragma unroll
            for (int it = 0; it < 4; it++)
                *(uint4*)&Aw[(ar + it * 32) * AS_LD + ac4 * 4] =
                    make_uint4(f2tf32(ra[it].x), f2tf32(ra[it].y),
                               f2tf32(ra[it].z), f2tf32(ra[it].w));
#pragma unroll
            for (int it = 0; it < 4; it++)
                *(uint4*)&Bw[(br + it * 8) * BS_LD + bc4 * 4] =
                    make_uint4(f2tf32(rb[it].x), f2tf32(rb[it].y),
                               f2tf32(rb[it].z), f2tf32(rb[it].w));
            __syncthreads();
            p = q;
        }
    }

#pragma unroll
    for (int mt = 0; mt < 4; mt++) {
#pragma unroll
        for (int nt = 0; nt < 4; nt++) {
            int row = bm + wm + mt * 16 + qr;
            int col = bn + wn + nt * 8 + 2 * qc;
            float2 r0 = make_float2(acc[mt][nt][0], acc[mt][nt][1]);
            float2 r1 = make_float2(acc[mt][nt][2], acc[mt][nt][3]);
            if (MODE == 0) {
                int b0 = row >> 11, l0 = row & (L_ - 1);
                int h = col >> 7, d = col & (HD_ - 1);
                *(float2*)(C + ((((size_t)b0 * H_ + h) * L_ + l0) * HD_ + d)) = r0;
                int row1 = row + 8;
                int b1 = row1 >> 11, l1 = row1 & (L_ - 1);
                *(float2*)(C + ((((size_t)b1 * H_ + h) * L_ + l1) * HD_ + d)) = r1;
            } else {
                *(float2*)(C + (size_t)row * N + col) = r0;
                *(float2*)(C + (size_t)(row + 8) * N + col) = r1;
            }
        }
    }
}

// ---------------------------------------------------------------------------
// RoPE in-place on q and k.
// ---------------------------------------------------------------------------
__global__ void rope_kernel(float* __restrict__ qb, float* __restrict__ kb)
{
    int idx = blockIdx.x * blockDim.x + threadIdx.x;
    if (idx >= B_ * H_ * L_ * 64) return;
    int j  = idx & 63;
    int l  = (idx >> 6) & (L_ - 1);
    int bh = idx >> 17;

    float freq = expf(-9.210340371976184f * (float)j * (1.0f / 64.0f));
    float ang = (float)l * freq;
    float s, c;
    sincosf(ang, &s, &c);

    size_t base = ((size_t)bh * L_ + l) * HD_ + j;
    float q1 = qb[base], q2 = qb[base + 64];
    qb[base]      = q1 * c - q2 * s;
    qb[base + 64] = q1 * s + q2 * c;
    float k1 = kb[base], k2 = kb[base + 64];
    kb[base]      = k1 * c - k2 * s;
    kb[base + 64] = k1 * s + k2 * c;
}

// ---------------------------------------------------------------------------
// Tensor-core attention + memory path (unchanged — verified at 7.1e-4).
// ---------------------------------------------------------------------------
#define QS_OFF 0
#define KS_OFF 16896
#define VS_OFF 25344
#define PS_OFF 34048
#define MS_OFF 16896
#define NS_OFF 34304
#define LDQ 132
#define LDK 132
#define LDV 136
#define LDP 68
#define LDM 136
#define ATTN_SMEM (42752 * 4)

__global__ __launch_bounds__(256, 1) void attn_tc(
    const float* __restrict__ qb, const float* __restrict__ kb,
    const float* __restrict__ vb, const float* __restrict__ gatep,
    const float* __restrict__ memp, const float* __restrict__ normp,
    float* __restrict__ cb)
{
    extern __shared__ float smf[];
    unsigned* smu = (unsigned*)smf;

    const int tid = threadIdx.x;
    const int w = tid >> 5, lane = tid & 31;
    const int qr = lane >> 2, qc = lane & 3;
    const int qt = blockIdx.x;
    const int bh = blockIdx.y;
    const int h  = bh & (H_ - 1);
    const int b  = bh >> 4;
    const int m0 = w * 16 + qr;

    const float* qblk  = qb + ((size_t)bh * L_ + qt * 128) * HD_;
    const float* kbase = kb + (size_t)bh * L_ * HD_;
    const float* vbase = vb + (size_t)bh * L_ * HD_;

#pragma unroll
    for (int it = 0; it < 16; it++) {
        int row = w + 8 * it;
        float4 v = *(const float4*)(qblk + (size_t)row * HD_ + lane * 4);
        *(uint4*)&smu[QS_OFF + row * LDQ + lane * 4] =
            make_uint4(f2tf32(v.x), f2tf32(v.y), f2tf32(v.z), f2tf32(v.w));
    }

    float o[16][4];
#pragma unroll
    for (int nt = 0; nt < 16; nt++)
#pragma unroll
        for (int u = 0; u < 4; u++) o[nt][u] = 0.f;
    float mrow0 = -1e30f, mrow1 = -1e30f;
    float lrow0 = 0.f, lrow1 = 0.f;

    const float scale = 0.08838834764831845f;

    for (int kt = 0; kt < 32; kt++) {
        const float* kblk = kbase + (size_t)kt * 64 * HD_;
        const float* vblk = vbase + (size_t)kt * 64 * HD_;
#pragma unroll
        for (int it = 0; it < 8; it++) {
            int row = w + 8 * it;
            float4 kv = *(const float4*)(kblk + (size_t)row * HD_ + lane * 4);
            *(uint4*)&smu[KS_OFF + row * LDK + lane * 4] =
                make_uint4(f2tf32(kv.x), f2tf32(kv.y), f2tf32(kv.z), f2tf32(kv.w));
            float4 vv = *(const float4*)(vblk + (size_t)row * HD_ + lane * 4);
            *(uint4*)&smu[VS_OFF + row * LDV + lane * 4] =
                make_uint4(f2tf32(vv.x), f2tf32(vv.y), f2tf32(vv.z), f2tf32(vv.w));
        }
        __syncthreads();

        float sa[8][4];
#pragma unroll
        for (int nt = 0; nt < 8; nt++)
#pragma unroll
            for (int u = 0; u < 4; u++) sa[nt][u] = 0.f;

#pragma unroll
        for (int ks = 0; ks < 16; ks++) {
            const int kb8 = ks * 8;
            unsigned a[4];
            a[0] = smu[QS_OFF + m0 * LDQ + kb8 + qc];
            a[1] = smu[QS_OFF + (m0 + 8) * LDQ + kb8 + qc];
            a[2] = smu[QS_OFF + m0 * LDQ + kb8 + qc + 4];
            a[3] = smu[QS_OFF + (m0 + 8) * LDQ + kb8 + qc + 4];
#pragma unroll
            for (int nt = 0; nt < 8; nt++) {
                int n = nt * 8 + qr;
                unsigned b0 = smu[KS_OFF + n * LDK + kb8 + qc];
                unsigned b1 = smu[KS_OFF + n * LDK + kb8 + qc + 4];
                mma_tf32(sa[nt], a, b0, b1);
            }
        }

        float cand0 = -1e30f, cand1 = -1e30f;
#pragma unroll
        for (int nt = 0; nt < 8; nt++) {
            cand0 = fmaxf(cand0, fmaxf(sa[nt][0], sa[nt][1]));
            cand1 = fmaxf(cand1, fmaxf(sa[nt][2], sa[nt][3]));
        }
        cand0 *= scale; cand1 *= scale;
        cand0 = fmaxf(cand0, __shfl_xor_sync(0xffffffffu, cand0, 1));
        cand0 = fmaxf(cand0, __shfl_xor_sync(0xffffffffu, cand0, 2));
        cand1 = fmaxf(cand1, __shfl_xor_sync(0xffffffffu, cand1, 1));
        cand1 = fmaxf(cand1, __shfl_xor_sync(0xffffffffu, cand1, 2));

        float newm0 = fmaxf(mrow0, cand0), newm1 = fmaxf(mrow1, cand1);
        float corr0 = __expf(mrow0 - newm0), corr1 = __expf(mrow1 - newm1);
        mrow0 = newm0; mrow1 = newm1;

        float psum0 = 0.f, psum1 = 0.f;
#pragma unroll
        for (int nt = 0; nt < 8; nt++) {
            float p0 = __expf(sa[nt][0] * scale - newm0);
            float p1 = __expf(sa[nt][1] * scale - newm0);
            float p2 = __expf(sa[nt][2] * scale - newm1);
            float p3 = __expf(sa[nt][3] * scale - newm1);
            psum0 += p0 + p1; psum1 += p2 + p3;
            float2 lo, hi;
            lo.x = __uint_as_float(f2tf32(p0)); lo.y = __uint_as_float(f2tf32(p1));
            hi.x = __uint_as_float(f2tf32(p2)); hi.y = __uint_as_float(f2tf32(p3));
            *(float2*)&smf[PS_OFF + m0 * LDP + nt * 8 + 2 * qc] = lo;
            *(float2*)&smf[PS_OFF + (m0 + 8) * LDP + nt * 8 + 2 * qc] = hi;
        }
        psum0 += __shfl_xor_sync(0xffffffffu, psum0, 1);
        psum0 += __shfl_xor_sync(0xffffffffu, psum0, 2);
        psum1 += __shfl_xor_sync(0xffffffffu, psum1, 1);
        psum1 += __shfl_xor_sync(0xffffffffu, psum1, 2);
        lrow0 = lrow0 * corr0 + psum0;
        lrow1 = lrow1 * corr1 + psum1;

#pragma unroll
        for (int nt = 0; nt < 16; nt++) {
            o[nt][0] *= corr0; o[nt][1] *= corr0;
            o[nt][2] *= corr1; o[nt][3] *= corr1;
        }
        __syncthreads();

#pragma unroll
        for (int ks = 0; ks < 8; ks++) {
            const int kb8 = ks * 8;
            unsigned a[4];
            a[0] = __float_as_uint(smf[PS_OFF + m0 * LDP + kb8 + qc]);
            a[1] = __float_as_uint(smf[PS_OFF + (m0 + 8) * LDP + kb8 + qc]);
            a[2] = __float_as_uint(smf[PS_OFF + m0 * LDP + kb8 + qc + 4]);
            a[3] = __float_as_uint(smf[PS_OFF + (m0 + 8) * LDP + kb8 + qc + 4]);
#pragma unroll
            for (int nt = 0; nt < 16; nt++) {
                int n = nt * 8 + qr;
                unsigned b0 = smu[VS_OFF + (kb8 + qc) * LDV + n];
                unsigned b1 = smu[VS_OFF + (kb8 + qc + 4) * LDV + n];
                mma_tf32(o[nt], a, b0, b1);
            }
        }
        __syncthreads();
    }

    // ================== epilogue: memory path ==================
    const float* mptr = memp + (size_t)bh * HD_ * HD_;
#pragma unroll
    for (int it = 0; it < 16; it++) {
        int row = w + 8 * it;
        float4 v = *(const float4*)(mptr + (size_t)row * HD_ + lane * 4);
        *(uint4*)&smu[MS_OFF + row * LDM + lane * 4] =
            make_uint4(f2tf32(v.x), f2tf32(v.y), f2tf32(v.z), f2tf32(v.w));
    }
    if (tid < 128) smf[NS_OFF + tid] = normp[(size_t)bh * HD_ + tid];

#pragma unroll
    for (int it = 0; it < 64; it++) {
        int e = tid + it * 256;
        int row = e >> 7, col = e & 127;
        float qv = smf[QS_OFF + row * LDQ + col];
        float qf = qv > 0.f ? qv + 1.f : __expf(qv);
        smu[QS_OFF + row * LDQ + col] = f2tf32(qf);
    }
    __syncthreads();

    float den0 = 0.f, den1 = 0.f;
#pragma unroll 8
    for (int j = 0; j < 32; j++) {
        int d = qc + 4 * j;
        float nv = smf[NS_OFF + d];
        den0 = fmaf(smf[QS_OFF + m0 * LDQ + d], nv, den0);
        den1 = fmaf(smf[QS_OFF + (m0 + 8) * LDQ + d], nv, den1);
    }
    den0 += __shfl_xor_sync(0xffffffffu, den0, 1);
    den0 += __shfl_xor_sync(0xffffffffu, den0, 2);
    den1 += __shfl_xor_sync(0xffffffffu, den1, 1);
    den1 += __shfl_xor_sync(0xffffffffu, den1, 2);

    const float g  = 1.f / (1.f + __expf(-gatep[h]));
    const float og = 1.f - g;
    const float invl0 = og / lrow0, invl1 = og / lrow1;
    const float invd0 = g / den0,   invd1 = g / den1;

    const int l0 = qt * 128 + m0;
    float* dst0 = cb + ((size_t)b * L_ + l0) * (H_ * HD_) + h * HD_;
    float* dst1 = cb + ((size_t)b * L_ + l0 + 8) * (H_ * HD_) + h * HD_;

#pragma unroll
    for (int pass = 0; pass < 2; pass++) {
        float ma[8][4];
#pragma unroll
        for (int nt = 0; nt < 8; nt++)
#pragma unroll
            for (int u = 0; u < 4; u++) ma[nt][u] = 0.f;

#pragma unroll
        for (int ks = 0; ks < 16; ks++) {
            const int kb8 = ks * 8;
            unsigned a[4];
            a[0] = smu[QS_OFF + m0 * LDQ + kb8 + qc];
            a[1] = smu[QS_OFF + (m0 + 8) * LDQ + kb8 + qc];
            a[2] = smu[QS_OFF + m0 * LDQ + kb8 + qc + 4];
            a[3] = smu[QS_OFF + (m0 + 8) * LDQ + kb8 + qc + 4];
#pragma unroll
            for (int nt = 0; nt < 8; nt++) {
                int n = (pass * 8 + nt) * 8 + qr;
                unsigned b0 = smu[MS_OFF + (kb8 + qc) * LDM + n];
                unsigned b1 = smu[MS_OFF + (kb8 + qc + 4) * LDM + n];
                mma_tf32(ma[nt], a, b0, b1);
            }
        }

#pragma unroll
        for (int nt = 0; nt < 8; nt++) {
            int gnt = pass * 8 + nt;
            int col = gnt * 8 + 2 * qc;
            float2 r0, r1;
            r0.x = ma[nt][0] * invd0 + o[gnt][0] * invl0;
            r0.y = ma[nt][1] * invd0 + o[gnt][1] * invl0;
            r1.x = ma[nt][2] * invd1 + o[gnt][2] * invl1;
            r1.y = ma[nt][3] * invd1 + o[gnt][3] * invl1;
            *(float2*)(dst0 + col) = r0;
            *(float2*)(dst1 + col) = r1;
        }
    }
}

// ---------------------------------------------------------------------------

extern "C" void kernel_launch(void* const* d_in, const int* in_sizes, int n_in,
                              void* d_out, int out_size)
{
    const float* x      = (const float*)d_in[0];
    const float* Wq     = (const float*)d_in[1];
    const float* Wk     = (const float*)d_in[2];
    const float* Wv     = (const float*)d_in[3];
    const float* Wo     = (const float*)d_in[4];
    const float* gate   = (const float*)d_in[5];
    const float* memory = (const float*)d_in[6];
    const float* norm   = (const float*)d_in[7];
    float* out = (float*)d_out;

    float *qb, *kb, *vb, *cb;
    cudaGetSymbolAddress((void**)&qb, g_q);
    cudaGetSymbolAddress((void**)&kb, g_k);
    cudaGetSymbolAddress((void**)&vb, g_v);
    cudaGetSymbolAddress((void**)&cb, g_c);

    cudaFuncSetAttribute(gemm_tf32<0>, cudaFuncAttributeMaxDynamicSharedMemorySize, GEMM_SMEM);
    cudaFuncSetAttribute(gemm_tf32<1>, cudaFuncAttributeMaxDynamicSharedMemorySize, GEMM_SMEM);

    dim3 gg(16, 32);   // N/128, M/128
    // Order: Q, K, rope, V, attn, O — puts a GEMM in ncu's fixed capture slot
    // (rope only depends on q,k; v is not touched by rope).
    gemm_tf32<0><<<gg, 256, GEMM_SMEM>>>(x, Wq, qb, B_ * L_, H_ * HD_, D_);
    gemm_tf32<0><<<gg, 256, GEMM_SMEM>>>(x, Wk, kb, B_ * L_, H_ * HD_, D_);

    int nrope = B_ * H_ * L_ * 64;
    rope_kernel<<<nrope / 256, 256>>>(qb, kb);

    gemm_tf32<0><<<gg, 256, GEMM_SMEM>>>(x, Wv, vb, B_ * L_, H_ * HD_, D_);

    cudaFuncSetAttribute(attn_tc, cudaFuncAttributeMaxDynamicSharedMemorySize, ATTN_SMEM);
    attn_tc<<<dim3(16, 32), 256, ATTN_SMEM>>>(qb, kb, vb, gate, memory, norm, cb);

    gemm_tf32<1><<<gg, 256, GEMM_SMEM>>>(cb, Wo, out, B_ * L_, H_ * HD_, D_);
}

// round 7
// speedup vs baseline: 1.1599x; 1.0740x over previous
#include <cuda_runtime.h>
#include <math.h>

#define B_  2
#define L_  2048
#define D_  2048
#define H_  16
#define HD_ 128

// Scratch (static __device__ — no runtime allocation)
__device__ float g_q[(size_t)B_ * H_ * L_ * HD_];
__device__ float g_k[(size_t)B_ * H_ * L_ * HD_];
__device__ float g_v[(size_t)B_ * H_ * L_ * HD_];
__device__ float g_c[(size_t)B_ * L_ * H_ * HD_];

__device__ __forceinline__ unsigned f2tf32(float f) {
    unsigned u;
    asm("cvt.rna.tf32.f32 %0, %1;" : "=r"(u) : "f"(f));
    return u;
}

__device__ __forceinline__ void mma_tf32(float* c, const unsigned* a,
                                         unsigned b0, unsigned b1) {
    asm volatile(
        "mma.sync.aligned.m16n8k8.row.col.f32.tf32.tf32.f32 "
        "{%0,%1,%2,%3},{%4,%5,%6,%7},{%8,%9},{%0,%1,%2,%3};\n"
        : "+f"(c[0]), "+f"(c[1]), "+f"(c[2]), "+f"(c[3])
        : "r"(a[0]), "r"(a[1]), "r"(a[2]), "r"(a[3]), "r"(b0), "r"(b1));
}

__device__ __forceinline__ void cp16(void* smp, const void* g) {
    unsigned s = (unsigned)__cvta_generic_to_shared(smp);
    asm volatile("cp.async.cg.shared.global [%0], [%1], 16;" :: "r"(s), "l"(g));
}

// ---------------------------------------------------------------------------
// TF32 tensor-core GEMM v3: round-6 layout (BK=32, 64x32 warp tiles,
// AS_LD=36 / BS_LD=136 conflict-free), cp.async 3-stage pipeline instead of
// register staging -> regs <=128 -> 2 CTAs/SM. fp32 in smem, cvt.rna at
// fragment load (identical rounding sequence to round 6).
// MODE 0: scatter epilogue to (B,H,L,hd). MODE 1: plain row-major.
// ---------------------------------------------------------------------------
#define AS_LD 36
#define BS_LD 136
#define ST_A (128 * AS_LD)          // 4608 words
#define ST_B (32 * BS_LD)           // 4352 words
#define ST_W (ST_A + ST_B)          // 8960 words = 35840 B
#define GEMM_SMEM (3 * ST_W * 4)    // 107520 B

template <int MODE>
__global__ __launch_bounds__(256, 2) void gemm_tf32(
    const float* __restrict__ A, const float* __restrict__ Bm,
    float* __restrict__ C, int M, int N, int K)
{
    extern __shared__ float smf[];

    const int tid  = threadIdx.x;
    const int warp = tid >> 5, lane = tid & 31;
    const int qr = lane >> 2, qc = lane & 3;
    const int wm = (warp & 1) * 64;
    const int wn = (warp >> 1) * 32;
    const int bm = blockIdx.y * 128, bn = blockIdx.x * 128;

    // cp.async mapping: 4 x 16B for A and 4 x 16B for B per thread per stage
    const int rA = tid >> 3, cA = (tid & 7) * 4;      // A rows rA+32*it
    const int rB = tid >> 5, cB = (tid & 31) * 4;     // B rows rB+8*it

    const float* Agl = A + (size_t)(bm + rA) * K + cA;
    const float* Bgl = Bm + (size_t)rB * N + bn + cB;

    float acc[4][4][4];
#pragma unroll
    for (int mt = 0; mt < 4; mt++)
#pragma unroll
        for (int nt = 0; nt < 4; nt++)
#pragma unroll
            for (int u = 0; u < 4; u++) acc[mt][nt][u] = 0.f;

    const int NCHUNK = K >> 5;   // 64

    auto issue = [&](int s, int k0) {
        float* As = smf + s * ST_W;
        float* Bs = As + ST_A;
#pragma unroll
        for (int it = 0; it < 4; it++)
            cp16(&As[(rA + it * 32) * AS_LD + cA], Agl + (size_t)(it * 32) * K + k0);
#pragma unroll
        for (int it = 0; it < 4; it++)
            cp16(&Bs[(rB + it * 8) * BS_LD + cB], Bgl + (size_t)(k0 + it * 8) * N);
        asm volatile("cp.async.commit_group;");
    };

    issue(0, 0);
    issue(1, 32);

    int cur = 0, pf = 2;
    for (int ch = 0; ch < NCHUNK; ch++) {
        asm volatile("cp.async.wait_group 1;");
        __syncthreads();

        if (ch + 2 < NCHUNK) {
            issue(pf, (ch + 2) << 5);
        } else {
            asm volatile("cp.async.commit_group;");
        }

        const float* As = smf + cur * ST_W;
        const float* Bs = As + ST_A;

#pragma unroll
        for (int s = 0; s < 4; s++) {
            const int kb = s * 8;
            unsigned a[4][4], b[4][2];
#pragma unroll
            for (int mt = 0; mt < 4; mt++) {
                int m = wm + mt * 16 + qr;
                a[mt][0] = f2tf32(As[m * AS_LD + kb + qc]);
                a[mt][1] = f2tf32(As[(m + 8) * AS_LD + kb + qc]);
                a[mt][2] = f2tf32(As[m * AS_LD + kb + qc + 4]);
                a[mt][3] = f2tf32(As[(m + 8) * AS_LD + kb + qc + 4]);
            }
#pragma unroll
            for (int nt = 0; nt < 4; nt++) {
                int n = wn + nt * 8 + qr;
                b[nt][0] = f2tf32(Bs[(kb + qc) * BS_LD + n]);
                b[nt][1] = f2tf32(Bs[(kb + qc + 4) * BS_LD + n]);
            }
#pragma unroll
            for (int mt = 0; mt < 4; mt++)
#pragma unroll
                for (int nt = 0; nt < 4; nt++)
                    mma_tf32(acc[mt][nt], a[mt], b[nt][0], b[nt][1]);
        }

        cur = (cur == 2) ? 0 : cur + 1;
        pf  = (pf  == 2) ? 0 : pf  + 1;
    }

    // epilogue: c0,c1 at (row, 2qc), c2,c3 at (row+8, 2qc)
#pragma unroll
    for (int mt = 0; mt < 4; mt++) {
#pragma unroll
        for (int nt = 0; nt < 4; nt++) {
            int row = bm + wm + mt * 16 + qr;
            int col = bn + wn + nt * 8 + 2 * qc;
            float2 r0 = make_float2(acc[mt][nt][0], acc[mt][nt][1]);
            float2 r1 = make_float2(acc[mt][nt][2], acc[mt][nt][3]);
            if (MODE == 0) {
                int b0 = row >> 11, l0 = row & (L_ - 1);
                int h = col >> 7, d = col & (HD_ - 1);
                *(float2*)(C + ((((size_t)b0 * H_ + h) * L_ + l0) * HD_ + d)) = r0;
                int row1 = row + 8;
                int b1 = row1 >> 11, l1 = row1 & (L_ - 1);
                *(float2*)(C + ((((size_t)b1 * H_ + h) * L_ + l1) * HD_ + d)) = r1;
            } else {
                *(float2*)(C + (size_t)row * N + col) = r0;
                *(float2*)(C + (size_t)(row + 8) * N + col) = r1;
            }
        }
    }
}

// ---------------------------------------------------------------------------
// RoPE in-place on q and k.
// ---------------------------------------------------------------------------
__global__ void rope_kernel(float* __restrict__ qb, float* __restrict__ kb)
{
    int idx = blockIdx.x * blockDim.x + threadIdx.x;
    if (idx >= B_ * H_ * L_ * 64) return;
    int j  = idx & 63;
    int l  = (idx >> 6) & (L_ - 1);
    int bh = idx >> 17;

    float freq = expf(-9.210340371976184f * (float)j * (1.0f / 64.0f));
    float ang = (float)l * freq;
    float s, c;
    sincosf(ang, &s, &c);

    size_t base = ((size_t)bh * L_ + l) * HD_ + j;
    float q1 = qb[base], q2 = qb[base + 64];
    qb[base]      = q1 * c - q2 * s;
    qb[base + 64] = q1 * s + q2 * c;
    float k1 = kb[base], k2 = kb[base + 64];
    kb[base]      = k1 * c - k2 * s;
    kb[base + 64] = k1 * s + k2 * c;
}

// ---------------------------------------------------------------------------
// Tensor-core attention + memory path (unchanged — verified at 7.1e-4).
// ---------------------------------------------------------------------------
#define QS_OFF 0
#define KS_OFF 16896
#define VS_OFF 25344
#define PS_OFF 34048
#define MS_OFF 16896
#define NS_OFF 34304
#define LDQ 132
#define LDK 132
#define LDV 136
#define LDP 68
#define LDM 136
#define ATTN_SMEM (42752 * 4)

__global__ __launch_bounds__(256, 1) void attn_tc(
    const float* __restrict__ qb, const float* __restrict__ kb,
    const float* __restrict__ vb, const float* __restrict__ gatep,
    const float* __restrict__ memp, const float* __restrict__ normp,
    float* __restrict__ cb)
{
    extern __shared__ float smf[];
    unsigned* smu = (unsigned*)smf;

    const int tid = threadIdx.x;
    const int w = tid >> 5, lane = tid & 31;
    const int qr = lane >> 2, qc = lane & 3;
    const int qt = blockIdx.x;
    const int bh = blockIdx.y;
    const int h  = bh & (H_ - 1);
    const int b  = bh >> 4;
    const int m0 = w * 16 + qr;

    const float* qblk  = qb + ((size_t)bh * L_ + qt * 128) * HD_;
    const float* kbase = kb + (size_t)bh * L_ * HD_;
    const float* vbase = vb + (size_t)bh * L_ * HD_;

#pragma unroll
    for (int it = 0; it < 16; it++) {
        int row = w + 8 * it;
        float4 v = *(const float4*)(qblk + (size_t)row * HD_ + lane * 4);
        *(uint4*)&smu[QS_OFF + row * LDQ + lane * 4] =
            make_uint4(f2tf32(v.x), f2tf32(v.y), f2tf32(v.z), f2tf32(v.w));
    }

    float o[16][4];
#pragma unroll
    for (int nt = 0; nt < 16; nt++)
#pragma unroll
        for (int u = 0; u < 4; u++) o[nt][u] = 0.f;
    float mrow0 = -1e30f, mrow1 = -1e30f;
    float lrow0 = 0.f, lrow1 = 0.f;

    const float scale = 0.08838834764831845f;

    for (int kt = 0; kt < 32; kt++) {
        const float* kblk = kbase + (size_t)kt * 64 * HD_;
        const float* vblk = vbase + (size_t)kt * 64 * HD_;
#pragma unroll
        for (int it = 0; it < 8; it++) {
            int row = w + 8 * it;
            float4 kv = *(const float4*)(kblk + (size_t)row * HD_ + lane * 4);
            *(uint4*)&smu[KS_OFF + row * LDK + lane * 4] =
                make_uint4(f2tf32(kv.x), f2tf32(kv.y), f2tf32(kv.z), f2tf32(kv.w));
            float4 vv = *(const float4*)(vblk + (size_t)row * HD_ + lane * 4);
            *(uint4*)&smu[VS_OFF + row * LDV + lane * 4] =
                make_uint4(f2tf32(vv.x), f2tf32(vv.y), f2tf32(vv.z), f2tf32(vv.w));
        }
        __syncthreads();

        float sa[8][4];
#pragma unroll
        for (int nt = 0; nt < 8; nt++)
#pragma unroll
            for (int u = 0; u < 4; u++) sa[nt][u] = 0.f;

#pragma unroll
        for (int ks = 0; ks < 16; ks++) {
            const int kb8 = ks * 8;
            unsigned a[4];
            a[0] = smu[QS_OFF + m0 * LDQ + kb8 + qc];
            a[1] = smu[QS_OFF + (m0 + 8) * LDQ + kb8 + qc];
            a[2] = smu[QS_OFF + m0 * LDQ + kb8 + qc + 4];
            a[3] = smu[QS_OFF + (m0 + 8) * LDQ + kb8 + qc + 4];
#pragma unroll
            for (int nt = 0; nt < 8; nt++) {
                int n = nt * 8 + qr;
                unsigned b0 = smu[KS_OFF + n * LDK + kb8 + qc];
                unsigned b1 = smu[KS_OFF + n * LDK + kb8 + qc + 4];
                mma_tf32(sa[nt], a, b0, b1);
            }
        }

        float cand0 = -1e30f, cand1 = -1e30f;
#pragma unroll
        for (int nt = 0; nt < 8; nt++) {
            cand0 = fmaxf(cand0, fmaxf(sa[nt][0], sa[nt][1]));
            cand1 = fmaxf(cand1, fmaxf(sa[nt][2], sa[nt][3]));
        }
        cand0 *= scale; cand1 *= scale;
        cand0 = fmaxf(cand0, __shfl_xor_sync(0xffffffffu, cand0, 1));
        cand0 = fmaxf(cand0, __shfl_xor_sync(0xffffffffu, cand0, 2));
        cand1 = fmaxf(cand1, __shfl_xor_sync(0xffffffffu, cand1, 1));
        cand1 = fmaxf(cand1, __shfl_xor_sync(0xffffffffu, cand1, 2));

        float newm0 = fmaxf(mrow0, cand0), newm1 = fmaxf(mrow1, cand1);
        float corr0 = __expf(mrow0 - newm0), corr1 = __expf(mrow1 - newm1);
        mrow0 = newm0; mrow1 = newm1;

        float psum0 = 0.f, psum1 = 0.f;
#pragma unroll
        for (int nt = 0; nt < 8; nt++) {
            float p0 = __expf(sa[nt][0] * scale - newm0);
            float p1 = __expf(sa[nt][1] * scale - newm0);
            float p2 = __expf(sa[nt][2] * scale - newm1);
            float p3 = __expf(sa[nt][3] * scale - newm1);
            psum0 += p0 + p1; psum1 += p2 + p3;
            float2 lo, hi;
            lo.x = __uint_as_float(f2tf32(p0)); lo.y = __uint_as_float(f2tf32(p1));
            hi.x = __uint_as_float(f2tf32(p2)); hi.y = __uint_as_float(f2tf32(p3));
            *(float2*)&smf[PS_OFF + m0 * LDP + nt * 8 + 2 * qc] = lo;
            *(float2*)&smf[PS_OFF + (m0 + 8) * LDP + nt * 8 + 2 * qc] = hi;
        }
        psum0 += __shfl_xor_sync(0xffffffffu, psum0, 1);
        psum0 += __shfl_xor_sync(0xffffffffu, psum0, 2);
        psum1 += __shfl_xor_sync(0xffffffffu, psum1, 1);
        psum1 += __shfl_xor_sync(0xffffffffu, psum1, 2);
        lrow0 = lrow0 * corr0 + psum0;
        lrow1 = lrow1 * corr1 + psum1;

#pragma unroll
        for (int nt = 0; nt < 16; nt++) {
            o[nt][0] *= corr0; o[nt][1] *= corr0;
            o[nt][2] *= corr1; o[nt][3] *= corr1;
        }
        __syncthreads();

#pragma unroll
        for (int ks = 0; ks < 8; ks++) {
            const int kb8 = ks * 8;
            unsigned a[4];
            a[0] = __float_as_uint(smf[PS_OFF + m0 * LDP + kb8 + qc]);
            a[1] = __float_as_uint(smf[PS_OFF + (m0 + 8) * LDP + kb8 + qc]);
            a[2] = __float_as_uint(smf[PS_OFF + m0 * LDP + kb8 + qc + 4]);
            a[3] = __float_as_uint(smf[PS_OFF + (m0 + 8) * LDP + kb8 + qc + 4]);
#pragma unroll
            for (int nt = 0; nt < 16; nt++) {
                int n = nt * 8 + qr;
                unsigned b0 = smu[VS_OFF + (kb8 + qc) * LDV + n];
                unsigned b1 = smu[VS_OFF + (kb8 + qc + 4) * LDV + n];
                mma_tf32(o[nt], a, b0, b1);
            }
        }
        __syncthreads();
    }

    // ================== epilogue: memory path ==================
    const float* mptr = memp + (size_t)bh * HD_ * HD_;
#pragma unroll
    for (int it = 0; it < 16; it++) {
        int row = w + 8 * it;
        float4 v = *(const float4*)(mptr + (size_t)row * HD_ + lane * 4);
        *(uint4*)&smu[MS_OFF + row * LDM + lane * 4] =
            make_uint4(f2tf32(v.x), f2tf32(v.y), f2tf32(v.z), f2tf32(v.w));
    }
    if (tid < 128) smf[NS_OFF + tid] = normp[(size_t)bh * HD_ + tid];

#pragma unroll
    for (int it = 0; it < 64; it++) {
        int e = tid + it * 256;
        int row = e >> 7, col = e & 127;
        float qv = smf[QS_OFF + row * LDQ + col];
        float qf = qv > 0.f ? qv + 1.f : __expf(qv);
        smu[QS_OFF + row * LDQ + col] = f2tf32(qf);
    }
    __syncthreads();

    float den0 = 0.f, den1 = 0.f;
#pragma unroll 8
    for (int j = 0; j < 32; j++) {
        int d = qc + 4 * j;
        float nv = smf[NS_OFF + d];
        den0 = fmaf(smf[QS_OFF + m0 * LDQ + d], nv, den0);
        den1 = fmaf(smf[QS_OFF + (m0 + 8) * LDQ + d], nv, den1);
    }
    den0 += __shfl_xor_sync(0xffffffffu, den0, 1);
    den0 += __shfl_xor_sync(0xffffffffu, den0, 2);
    den1 += __shfl_xor_sync(0xffffffffu, den1, 1);
    den1 += __shfl_xor_sync(0xffffffffu, den1, 2);

    const float g  = 1.f / (1.f + __expf(-gatep[h]));
    const float og = 1.f - g;
    const float invl0 = og / lrow0, invl1 = og / lrow1;
    const float invd0 = g / den0,   invd1 = g / den1;

    const int l0 = qt * 128 + m0;
    float* dst0 = cb + ((size_t)b * L_ + l0) * (H_ * HD_) + h * HD_;
    float* dst1 = cb + ((size_t)b * L_ + l0 + 8) * (H_ * HD_) + h * HD_;

#pragma unroll
    for (int pass = 0; pass < 2; pass++) {
        float ma[8][4];
#pragma unroll
        for (int nt = 0; nt < 8; nt++)
#pragma unroll
            for (int u = 0; u < 4; u++) ma[nt][u] = 0.f;

#pragma unroll
        for (int ks = 0; ks < 16; ks++) {
            const int kb8 = ks * 8;
            unsigned a[4];
            a[0] = smu[QS_OFF + m0 * LDQ + kb8 + qc];
            a[1] = smu[QS_OFF + (m0 + 8) * LDQ + kb8 + qc];
            a[2] = smu[QS_OFF + m0 * LDQ + kb8 + qc + 4];
            a[3] = smu[QS_OFF + (m0 + 8) * LDQ + kb8 + qc + 4];
#pragma unroll
            for (int nt = 0; nt < 8; nt++) {
                int n = (pass * 8 + nt) * 8 + qr;
                unsigned b0 = smu[MS_OFF + (kb8 + qc) * LDM + n];
                unsigned b1 = smu[MS_OFF + (kb8 + qc + 4) * LDM + n];
                mma_tf32(ma[nt], a, b0, b1);
            }
        }

#pragma unroll
        for (int nt = 0; nt < 8; nt++) {
            int gnt = pass * 8 + nt;
            int col = gnt * 8 + 2 * qc;
            float2 r0, r1;
            r0.x = ma[nt][0] * invd0 + o[gnt][0] * invl0;
            r0.y = ma[nt][1] * invd0 + o[gnt][1] * invl0;
            r1.x = ma[nt][2] * invd1 + o[gnt][2] * invl1;
            r1.y = ma[nt][3] * invd1 + o[gnt][3] * invl1;
            *(float2*)(dst0 + col) = r0;
            *(float2*)(dst1 + col) = r1;
        }
    }
}

// ---------------------------------------------------------------------------

extern "C" void kernel_launch(void* const* d_in, const int* in_sizes, int n_in,
                              void* d_out, int out_size)
{
    const float* x      = (const float*)d_in[0];
    const float* Wq     = (const float*)d_in[1];
    const float* Wk     = (const float*)d_in[2];
    const float* Wv     = (const float*)d_in[3];
    const float* Wo     = (const float*)d_in[4];
    const float* gate   = (const float*)d_in[5];
    const float* memory = (const float*)d_in[6];
    const float* norm   = (const float*)d_in[7];
    float* out = (float*)d_out;

    float *qb, *kb, *vb, *cb;
    cudaGetSymbolAddress((void**)&qb, g_q);
    cudaGetSymbolAddress((void**)&kb, g_k);
    cudaGetSymbolAddress((void**)&vb, g_v);
    cudaGetSymbolAddress((void**)&cb, g_c);

    cudaFuncSetAttribute(gemm_tf32<0>, cudaFuncAttributeMaxDynamicSharedMemorySize, GEMM_SMEM);
    cudaFuncSetAttribute(gemm_tf32<1>, cudaFuncAttributeMaxDynamicSharedMemorySize, GEMM_SMEM);

    dim3 gg(16, 32);   // N/128, M/128
    gemm_tf32<0><<<gg, 256, GEMM_SMEM>>>(x, Wq, qb, B_ * L_, H_ * HD_, D_);
    gemm_tf32<0><<<gg, 256, GEMM_SMEM>>>(x, Wk, kb, B_ * L_, H_ * HD_, D_);

    int nrope = B_ * H_ * L_ * 64;
    rope_kernel<<<nrope / 256, 256>>>(qb, kb);

    gemm_tf32<0><<<gg, 256, GEMM_SMEM>>>(x, Wv, vb, B_ * L_, H_ * HD_, D_);

    cudaFuncSetAttribute(attn_tc, cudaFuncAttributeMaxDynamicSharedMemorySize, ATTN_SMEM);
    attn_tc<<<dim3(16, 32), 256, ATTN_SMEM>>>(qb, kb, vb, gate, memory, norm, cb);

    gemm_tf32<1><<<gg, 256, GEMM_SMEM>>>(cb, Wo, out, B_ * L_, H_ * HD_, D_);
}

// round 8
// speedup vs baseline: 1.2318x; 1.0620x over previous
#include <cuda_runtime.h>
#include <math.h>

#define B_  2
#define L_  2048
#define D_  2048
#define H_  16
#define HD_ 128

// Scratch (static __device__ — no runtime allocation)
__device__ float g_q[(size_t)B_ * H_ * L_ * HD_];
__device__ float g_k[(size_t)B_ * H_ * L_ * HD_];
__device__ float g_v[(size_t)B_ * H_ * L_ * HD_];
__device__ float g_c[(size_t)B_ * L_ * H_ * HD_];
__device__ float g_xt[(size_t)B_ * L_ * D_];          // x rounded to tf32
__device__ float g_w0[(size_t)D_ * H_ * HD_];         // Wq tf32
__device__ float g_w1[(size_t)D_ * H_ * HD_];         // Wk tf32
__device__ float g_w2[(size_t)D_ * H_ * HD_];         // Wv tf32
__device__ float g_w3[(size_t)D_ * H_ * HD_];         // Wo tf32

__device__ __forceinline__ unsigned f2tf32(float f) {
    unsigned u;
    asm("cvt.rna.tf32.f32 %0, %1;" : "=r"(u) : "f"(f));
    return u;
}
__device__ __forceinline__ float rnd(float f) { return __uint_as_float(f2tf32(f)); }

__device__ __forceinline__ void mma_tf32(float* c, const unsigned* a,
                                         unsigned b0, unsigned b1) {
    asm volatile(
        "mma.sync.aligned.m16n8k8.row.col.f32.tf32.tf32.f32 "
        "{%0,%1,%2,%3},{%4,%5,%6,%7},{%8,%9},{%0,%1,%2,%3};\n"
        : "+f"(c[0]), "+f"(c[1]), "+f"(c[2]), "+f"(c[3])
        : "r"(a[0]), "r"(a[1]), "r"(a[2]), "r"(a[3]), "r"(b0), "r"(b1));
}

__device__ __forceinline__ void cp16(void* smp, const void* g) {
    unsigned s = (unsigned)__cvta_generic_to_shared(smp);
    asm volatile("cp.async.cg.shared.global [%0], [%1], 16;" :: "r"(s), "l"(g));
}

// ---------------------------------------------------------------------------
// Elementwise fp32 -> tf32-rounded fp32 (bit pattern), float4 grid-stride.
// ---------------------------------------------------------------------------
__global__ void cvt_tf32_kernel(const float4* __restrict__ in,
                                float4* __restrict__ out, int n4)
{
    int i = blockIdx.x * blockDim.x + threadIdx.x;
    int stride = gridDim.x * blockDim.x;
    for (; i < n4; i += stride) {
        float4 v = in[i];
        out[i] = make_float4(rnd(v.x), rnd(v.y), rnd(v.z), rnd(v.w));
    }
}

// ---------------------------------------------------------------------------
// TF32 GEMM v4: inputs already tf32-rounded in gmem — NO cvt in kernel.
// cp.async 3-stage, BK=32, 2 CTAs/SM, conflict-free AS_LD=36 / BS_LD=136.
// MODE 0: scatter to (B,H,L,hd). MODE 1: row-major. MODE 2: scatter + round.
// ---------------------------------------------------------------------------
#define AS_LD 36
#define BS_LD 136
#define ST_A (128 * AS_LD)
#define ST_B (32 * BS_LD)
#define ST_W (ST_A + ST_B)
#define GEMM_SMEM (3 * ST_W * 4)    // 107520 B

template <int MODE>
__global__ __launch_bounds__(256, 2) void gemm_tf32(
    const float* __restrict__ A, const float* __restrict__ Bm,
    float* __restrict__ C, int M, int N, int K)
{
    extern __shared__ unsigned smu[];

    const int tid  = threadIdx.x;
    const int warp = tid >> 5, lane = tid & 31;
    const int qr = lane >> 2, qc = lane & 3;
    const int wm = (warp & 1) * 64;
    const int wn = (warp >> 1) * 32;
    const int bm = blockIdx.y * 128, bn = blockIdx.x * 128;

    const int rA = tid >> 3, cA = (tid & 7) * 4;
    const int rB = tid >> 5, cB = (tid & 31) * 4;

    const float* Agl = A + (size_t)(bm + rA) * K + cA;
    const float* Bgl = Bm + (size_t)rB * N + bn + cB;

    float acc[4][4][4];
#pragma unroll
    for (int mt = 0; mt < 4; mt++)
#pragma unroll
        for (int nt = 0; nt < 4; nt++)
#pragma unroll
            for (int u = 0; u < 4; u++) acc[mt][nt][u] = 0.f;

    const int NCHUNK = K >> 5;

    auto issue = [&](int s, int k0) {
        unsigned* As = smu + s * ST_W;
        unsigned* Bs = As + ST_A;
#pragma unroll
        for (int it = 0; it < 4; it++)
            cp16(&As[(rA + it * 32) * AS_LD + cA], Agl + (size_t)(it * 32) * K + k0);
#pragma unroll
        for (int it = 0; it < 4; it++)
            cp16(&Bs[(rB + it * 8) * BS_LD + cB], Bgl + (size_t)(k0 + it * 8) * N);
        asm volatile("cp.async.commit_group;");
    };

    issue(0, 0);
    issue(1, 32);

    int cur = 0, pf = 2;
    for (int ch = 0; ch < NCHUNK; ch++) {
        asm volatile("cp.async.wait_group 1;");
        __syncthreads();

        if (ch + 2 < NCHUNK) {
            issue(pf, (ch + 2) << 5);
        } else {
            asm volatile("cp.async.commit_group;");
        }

        const unsigned* As = smu + cur * ST_W;
        const unsigned* Bs = As + ST_A;

#pragma unroll
        for (int s = 0; s < 4; s++) {
            const int kb = s * 8;
            unsigned a[4][4], b[4][2];
#pragma unroll
            for (int mt = 0; mt < 4; mt++) {
                int m = wm + mt * 16 + qr;
                a[mt][0] = As[m * AS_LD + kb + qc];
                a[mt][1] = As[(m + 8) * AS_LD + kb + qc];
                a[mt][2] = As[m * AS_LD + kb + qc + 4];
                a[mt][3] = As[(m + 8) * AS_LD + kb + qc + 4];
            }
#pragma unroll
            for (int nt = 0; nt < 4; nt++) {
                int n = wn + nt * 8 + qr;
                b[nt][0] = Bs[(kb + qc) * BS_LD + n];
                b[nt][1] = Bs[(kb + qc + 4) * BS_LD + n];
            }
#pragma unroll
            for (int mt = 0; mt < 4; mt++)
#pragma unroll
                for (int nt = 0; nt < 4; nt++)
                    mma_tf32(acc[mt][nt], a[mt], b[nt][0], b[nt][1]);
        }

        cur = (cur == 2) ? 0 : cur + 1;
        pf  = (pf  == 2) ? 0 : pf  + 1;
    }

#pragma unroll
    for (int mt = 0; mt < 4; mt++) {
#pragma unroll
        for (int nt = 0; nt < 4; nt++) {
            int row = bm + wm + mt * 16 + qr;
            int col = bn + wn + nt * 8 + 2 * qc;
            float2 r0, r1;
            if (MODE == 2) {
                r0 = make_float2(rnd(acc[mt][nt][0]), rnd(acc[mt][nt][1]));
                r1 = make_float2(rnd(acc[mt][nt][2]), rnd(acc[mt][nt][3]));
            } else {
                r0 = make_float2(acc[mt][nt][0], acc[mt][nt][1]);
                r1 = make_float2(acc[mt][nt][2], acc[mt][nt][3]);
            }
            if (MODE == 0 || MODE == 2) {
                int b0 = row >> 11, l0 = row & (L_ - 1);
                int h = col >> 7, d = col & (HD_ - 1);
                *(float2*)(C + ((((size_t)b0 * H_ + h) * L_ + l0) * HD_ + d)) = r0;
                int row1 = row + 8;
                int b1 = row1 >> 11, l1 = row1 & (L_ - 1);
                *(float2*)(C + ((((size_t)b1 * H_ + h) * L_ + l1) * HD_ + d)) = r1;
            } else {
                *(float2*)(C + (size_t)row * N + col) = r0;
                *(float2*)(C + (size_t)(row + 8) * N + col) = r1;
            }
        }
    }
}

// ---------------------------------------------------------------------------
// RoPE in-place; stores tf32-rounded results (attention consumes raw).
// ---------------------------------------------------------------------------
__global__ void rope_kernel(float* __restrict__ qb, float* __restrict__ kb)
{
    int idx = blockIdx.x * blockDim.x + threadIdx.x;
    if (idx >= B_ * H_ * L_ * 64) return;
    int j  = idx & 63;
    int l  = (idx >> 6) & (L_ - 1);
    int bh = idx >> 17;

    float freq = expf(-9.210340371976184f * (float)j * (1.0f / 64.0f));
    float ang = (float)l * freq;
    float s, c;
    sincosf(ang, &s, &c);

    size_t base = ((size_t)bh * L_ + l) * HD_ + j;
    float q1 = qb[base], q2 = qb[base + 64];
    qb[base]      = rnd(q1 * c - q2 * s);
    qb[base + 64] = rnd(q1 * s + q2 * c);
    float k1 = kb[base], k2 = kb[base + 64];
    kb[base]      = rnd(k1 * c - k2 * s);
    kb[base + 64] = rnd(k1 * s + k2 * c);
}

// ---------------------------------------------------------------------------
// Tensor-core attention + memory path. q/k/v arrive tf32-rounded -> raw
// 16B tile copies (no cvt). Output cb stored tf32-rounded for final GEMM.
// ---------------------------------------------------------------------------
#define QS_OFF 0
#define KS_OFF 16896
#define VS_OFF 25344
#define PS_OFF 34048
#define MS_OFF 16896
#define NS_OFF 34304
#define LDQ 132
#define LDK 132
#define LDV 136
#define LDP 68
#define LDM 136
#define ATTN_SMEM (42752 * 4)

__global__ __launch_bounds__(256, 1) void attn_tc(
    const float* __restrict__ qb, const float* __restrict__ kb,
    const float* __restrict__ vb, const float* __restrict__ gatep,
    const float* __restrict__ memp, const float* __restrict__ normp,
    float* __restrict__ cb)
{
    extern __shared__ float smf[];
    unsigned* smu = (unsigned*)smf;

    const int tid = threadIdx.x;
    const int w = tid >> 5, lane = tid & 31;
    const int qr = lane >> 2, qc = lane & 3;
    const int qt = blockIdx.x;
    const int bh = blockIdx.y;
    const int h  = bh & (H_ - 1);
    const int b  = bh >> 4;
    const int m0 = w * 16 + qr;

    const float* qblk  = qb + ((size_t)bh * L_ + qt * 128) * HD_;
    const float* kbase = kb + (size_t)bh * L_ * HD_;
    const float* vbase = vb + (size_t)bh * L_ * HD_;

#pragma unroll
    for (int it = 0; it < 16; it++) {
        int row = w + 8 * it;
        *(uint4*)&smu[QS_OFF + row * LDQ + lane * 4] =
            *(const uint4*)(qblk + (size_t)row * HD_ + lane * 4);
    }

    float o[16][4];
#pragma unroll
    for (int nt = 0; nt < 16; nt++)
#pragma unroll
        for (int u = 0; u < 4; u++) o[nt][u] = 0.f;
    float mrow0 = -1e30f, mrow1 = -1e30f;
    float lrow0 = 0.f, lrow1 = 0.f;

    const float scale = 0.08838834764831845f;

    for (int kt = 0; kt < 32; kt++) {
        const float* kblk = kbase + (size_t)kt * 64 * HD_;
        const float* vblk = vbase + (size_t)kt * 64 * HD_;
#pragma unroll
        for (int it = 0; it < 8; it++) {
            int row = w + 8 * it;
            *(uint4*)&smu[KS_OFF + row * LDK + lane * 4] =
                *(const uint4*)(kblk + (size_t)row * HD_ + lane * 4);
            *(uint4*)&smu[VS_OFF + row * LDV + lane * 4] =
                *(const uint4*)(vblk + (size_t)row * HD_ + lane * 4);
        }
        __syncthreads();

        float sa[8][4];
#pragma unroll
        for (int nt = 0; nt < 8; nt++)
#pragma unroll
            for (int u = 0; u < 4; u++) sa[nt][u] = 0.f;

#pragma unroll
        for (int ks = 0; ks < 16; ks++) {
            const int kb8 = ks * 8;
            unsigned a[4];
            a[0] = smu[QS_OFF + m0 * LDQ + kb8 + qc];
            a[1] = smu[QS_OFF + (m0 + 8) * LDQ + kb8 + qc];
            a[2] = smu[QS_OFF + m0 * LDQ + kb8 + qc + 4];
            a[3] = smu[QS_OFF + (m0 + 8) * LDQ + kb8 + qc + 4];
#pragma unroll
            for (int nt = 0; nt < 8; nt++) {
                int n = nt * 8 + qr;
                unsigned b0 = smu[KS_OFF + n * LDK + kb8 + qc];
                unsigned b1 = smu[KS_OFF + n * LDK + kb8 + qc + 4];
                mma_tf32(sa[nt], a, b0, b1);
            }
        }

        float cand0 = -1e30f, cand1 = -1e30f;
#pragma unroll
        for (int nt = 0; nt < 8; nt++) {
            cand0 = fmaxf(cand0, fmaxf(sa[nt][0], sa[nt][1]));
            cand1 = fmaxf(cand1, fmaxf(sa[nt][2], sa[nt][3]));
        }
        cand0 *= scale; cand1 *= scale;
        cand0 = fmaxf(cand0, __shfl_xor_sync(0xffffffffu, cand0, 1));
        cand0 = fmaxf(cand0, __shfl_xor_sync(0xffffffffu, cand0, 2));
        cand1 = fmaxf(cand1, __shfl_xor_sync(0xffffffffu, cand1, 1));
        cand1 = fmaxf(cand1, __shfl_xor_sync(0xffffffffu, cand1, 2));

        float newm0 = fmaxf(mrow0, cand0), newm1 = fmaxf(mrow1, cand1);
        float corr0 = __expf(mrow0 - newm0), corr1 = __expf(mrow1 - newm1);
        mrow0 = newm0; mrow1 = newm1;

        float psum0 = 0.f, psum1 = 0.f;
#pragma unroll
        for (int nt = 0; nt < 8; nt++) {
            float p0 = __expf(sa[nt][0] * scale - newm0);
            float p1 = __expf(sa[nt][1] * scale - newm0);
            float p2 = __expf(sa[nt][2] * scale - newm1);
            float p3 = __expf(sa[nt][3] * scale - newm1);
            psum0 += p0 + p1; psum1 += p2 + p3;
            float2 lo, hi;
            lo.x = rnd(p0); lo.y = rnd(p1);
            hi.x = rnd(p2); hi.y = rnd(p3);
            *(float2*)&smf[PS_OFF + m0 * LDP + nt * 8 + 2 * qc] = lo;
            *(float2*)&smf[PS_OFF + (m0 + 8) * LDP + nt * 8 + 2 * qc] = hi;
        }
        psum0 += __shfl_xor_sync(0xffffffffu, psum0, 1);
        psum0 += __shfl_xor_sync(0xffffffffu, psum0, 2);
        psum1 += __shfl_xor_sync(0xffffffffu, psum1, 1);
        psum1 += __shfl_xor_sync(0xffffffffu, psum1, 2);
        lrow0 = lrow0 * corr0 + psum0;
        lrow1 = lrow1 * corr1 + psum1;

#pragma unroll
        for (int nt = 0; nt < 16; nt++) {
            o[nt][0] *= corr0; o[nt][1] *= corr0;
            o[nt][2] *= corr1; o[nt][3] *= corr1;
        }
        __syncthreads();

#pragma unroll
        for (int ks = 0; ks < 8; ks++) {
            const int kb8 = ks * 8;
            unsigned a[4];
            a[0] = __float_as_uint(smf[PS_OFF + m0 * LDP + kb8 + qc]);
            a[1] = __float_as_uint(smf[PS_OFF + (m0 + 8) * LDP + kb8 + qc]);
            a[2] = __float_as_uint(smf[PS_OFF + m0 * LDP + kb8 + qc + 4]);
            a[3] = __float_as_uint(smf[PS_OFF + (m0 + 8) * LDP + kb8 + qc + 4]);
#pragma unroll
            for (int nt = 0; nt < 16; nt++) {
                int n = nt * 8 + qr;
                unsigned b0 = smu[VS_OFF + (kb8 + qc) * LDV + n];
                unsigned b1 = smu[VS_OFF + (kb8 + qc + 4) * LDV + n];
                mma_tf32(o[nt], a, b0, b1);
            }
        }
        __syncthreads();
    }

    // ================== epilogue: memory path ==================
    const float* mptr = memp + (size_t)bh * HD_ * HD_;
#pragma unroll
    for (int it = 0; it < 16; it++) {
        int row = w + 8 * it;
        float4 v = *(const float4*)(mptr + (size_t)row * HD_ + lane * 4);
        *(uint4*)&smu[MS_OFF + row * LDM + lane * 4] =
            make_uint4(f2tf32(v.x), f2tf32(v.y), f2tf32(v.z), f2tf32(v.w));
    }
    if (tid < 128) smf[NS_OFF + tid] = normp[(size_t)bh * HD_ + tid];

#pragma unroll
    for (int it = 0; it < 64; it++) {
        int e = tid + it * 256;
        int row = e >> 7, col = e & 127;
        float qv = smf[QS_OFF + row * LDQ + col];
        float qf = qv > 0.f ? qv + 1.f : __expf(qv);
        smu[QS_OFF + row * LDQ + col] = f2tf32(qf);
    }
    __syncthreads();

    float den0 = 0.f, den1 = 0.f;
#pragma unroll 8
    for (int j = 0; j < 32; j++) {
        int d = qc + 4 * j;
        float nv = smf[NS_OFF + d];
        den0 = fmaf(smf[QS_OFF + m0 * LDQ + d], nv, den0);
        den1 = fmaf(smf[QS_OFF + (m0 + 8) * LDQ + d], nv, den1);
    }
    den0 += __shfl_xor_sync(0xffffffffu, den0, 1);
    den0 += __shfl_xor_sync(0xffffffffu, den0, 2);
    den1 += __shfl_xor_sync(0xffffffffu, den1, 1);
    den1 += __shfl_xor_sync(0xffffffffu, den1, 2);

    const float g  = 1.f / (1.f + __expf(-gatep[h]));
    const float og = 1.f - g;
    const float invl0 = og / lrow0, invl1 = og / lrow1;
    const float invd0 = g / den0,   invd1 = g / den1;

    const int l0 = qt * 128 + m0;
    float* dst0 = cb + ((size_t)b * L_ + l0) * (H_ * HD_) + h * HD_;
    float* dst1 = cb + ((size_t)b * L_ + l0 + 8) * (H_ * HD_) + h * HD_;

#pragma unroll
    for (int pass = 0; pass < 2; pass++) {
        float ma[8][4];
#pragma unroll
        for (int nt = 0; nt < 8; nt++)
#pragma unroll
            for (int u = 0; u < 4; u++) ma[nt][u] = 0.f;

#pragma unroll
        for (int ks = 0; ks < 16; ks++) {
            const int kb8 = ks * 8;
            unsigned a[4];
            a[0] = smu[QS_OFF + m0 * LDQ + kb8 + qc];
            a[1] = smu[QS_OFF + (m0 + 8) * LDQ + kb8 + qc];
            a[2] = smu[QS_OFF + m0 * LDQ + kb8 + qc + 4];
            a[3] = smu[QS_OFF + (m0 + 8) * LDQ + kb8 + qc + 4];
#pragma unroll
            for (int nt = 0; nt < 8; nt++) {
                int n = (pass * 8 + nt) * 8 + qr;
                unsigned b0 = smu[MS_OFF + (kb8 + qc) * LDM + n];
                unsigned b1 = smu[MS_OFF + (kb8 + qc + 4) * LDM + n];
                mma_tf32(ma[nt], a, b0, b1);
            }
        }

#pragma unroll
        for (int nt = 0; nt < 8; nt++) {
            int gnt = pass * 8 + nt;
            int col = gnt * 8 + 2 * qc;
            float2 r0, r1;
            r0.x = rnd(ma[nt][0] * invd0 + o[gnt][0] * invl0);
            r0.y = rnd(ma[nt][1] * invd0 + o[gnt][1] * invl0);
            r1.x = rnd(ma[nt][2] * invd1 + o[gnt][2] * invl1);
            r1.y = rnd(ma[nt][3] * invd1 + o[gnt][3] * invl1);
            *(float2*)(dst0 + col) = r0;
            *(float2*)(dst1 + col) = r1;
        }
    }
}

// ---------------------------------------------------------------------------

extern "C" void kernel_launch(void* const* d_in, const int* in_sizes, int n_in,
                              void* d_out, int out_size)
{
    const float* x      = (const float*)d_in[0];
    const float* Wq     = (const float*)d_in[1];
    const float* Wk     = (const float*)d_in[2];
    const float* Wv     = (const float*)d_in[3];
    const float* Wo     = (const float*)d_in[4];
    const float* gate   = (const float*)d_in[5];
    const float* memory = (const float*)d_in[6];
    const float* norm   = (const float*)d_in[7];
    float* out = (float*)d_out;

    float *qb, *kb, *vb, *cb, *xt, *w0, *w1, *w2, *w3;
    cudaGetSymbolAddress((void**)&qb, g_q);
    cudaGetSymbolAddress((void**)&kb, g_k);
    cudaGetSymbolAddress((void**)&vb, g_v);
    cudaGetSymbolAddress((void**)&cb, g_c);
    cudaGetSymbolAddress((void**)&xt, g_xt);
    cudaGetSymbolAddress((void**)&w0, g_w0);
    cudaGetSymbolAddress((void**)&w1, g_w1);
    cudaGetSymbolAddress((void**)&w2, g_w2);
    cudaGetSymbolAddress((void**)&w3, g_w3);

    // Pre-round inputs to tf32 bit patterns (bit-identical to inline cvt)
    int n4x = (B_ * L_ * D_) / 4;          // 2097152
    int n4w = (D_ * H_ * HD_) / 4;         // 1048576
    cvt_tf32_kernel<<<2048, 256>>>((const float4*)x,  (float4*)xt, n4x);
    cvt_tf32_kernel<<<2048, 256>>>((const float4*)Wq, (float4*)w0, n4w);
    cvt_tf32_kernel<<<2048, 256>>>((const float4*)Wk, (float4*)w1, n4w);
    cvt_tf32_kernel<<<2048, 256>>>((const float4*)Wv, (float4*)w2, n4w);
    cvt_tf32_kernel<<<2048, 256>>>((const float4*)Wo, (float4*)w3, n4w);

    cudaFuncSetAttribute(gemm_tf32<0>, cudaFuncAttributeMaxDynamicSharedMemorySize, GEMM_SMEM);
    cudaFuncSetAttribute(gemm_tf32<1>, cudaFuncAttributeMaxDynamicSharedMemorySize, GEMM_SMEM);
    cudaFuncSetAttribute(gemm_tf32<2>, cudaFuncAttributeMaxDynamicSharedMemorySize, GEMM_SMEM);

    dim3 gg(16, 32);   // N/128, M/128
    gemm_tf32<0><<<gg, 256, GEMM_SMEM>>>(xt, w0, qb, B_ * L_, H_ * HD_, D_);
    gemm_tf32<0><<<gg, 256, GEMM_SMEM>>>(xt, w1, kb, B_ * L_, H_ * HD_, D_);

    int nrope = B_ * H_ * L_ * 64;
    rope_kernel<<<nrope / 256, 256>>>(qb, kb);

    gemm_tf32<2><<<gg, 256, GEMM_SMEM>>>(xt, w2, vb, B_ * L_, H_ * HD_, D_);

    cudaFuncSetAttribute(attn_tc, cudaFuncAttributeMaxDynamicSharedMemorySize, ATTN_SMEM);
    attn_tc<<<dim3(16, 32), 256, ATTN_SMEM>>>(qb, kb, vb, gate, memory, norm, cb);

    gemm_tf32<1><<<gg, 256, GEMM_SMEM>>>(cb, w3, out, B_ * L_, H_ * HD_, D_);
}

// round 10
// speedup vs baseline: 1.3151x; 1.0676x over previous
#include <cuda_runtime.h>
#include <math.h>

#define B_  2
#define L_  2048
#define D_  2048
#define H_  16
#define HD_ 128

// Scratch (static __device__ — no runtime allocation)
__device__ float g_q[(size_t)B_ * H_ * L_ * HD_];
__device__ float g_k[(size_t)B_ * H_ * L_ * HD_];
__device__ float g_v[(size_t)B_ * H_ * L_ * HD_];
__device__ float g_c[(size_t)B_ * L_ * H_ * HD_];
__device__ float g_xt[(size_t)B_ * L_ * D_];
__device__ float g_w0[(size_t)D_ * H_ * HD_];
__device__ float g_w1[(size_t)D_ * H_ * HD_];
__device__ float g_w2[(size_t)D_ * H_ * HD_];
__device__ float g_w3[(size_t)D_ * H_ * HD_];

__device__ __forceinline__ unsigned f2tf32(float f) {
    unsigned u;
    asm("cvt.rna.tf32.f32 %0, %1;" : "=r"(u) : "f"(f));
    return u;
}
__device__ __forceinline__ float rnd(float f) { return __uint_as_float(f2tf32(f)); }

__device__ __forceinline__ void mma_tf32(float* c, const unsigned* a,
                                         unsigned b0, unsigned b1) {
    asm volatile(
        "mma.sync.aligned.m16n8k8.row.col.f32.tf32.tf32.f32 "
        "{%0,%1,%2,%3},{%4,%5,%6,%7},{%8,%9},{%0,%1,%2,%3};\n"
        : "+f"(c[0]), "+f"(c[1]), "+f"(c[2]), "+f"(c[3])
        : "r"(a[0]), "r"(a[1]), "r"(a[2]), "r"(a[3]), "r"(b0), "r"(b1));
}

__device__ __forceinline__ void cp16(void* smp, const void* g) {
    unsigned s = (unsigned)__cvta_generic_to_shared(smp);
    asm volatile("cp.async.cg.shared.global [%0], [%1], 16;" :: "r"(s), "l"(g));
}

// ---------------------------------------------------------------------------
// One fused tf32-rounding kernel for x, Wq, Wk, Wv, Wo.
// ---------------------------------------------------------------------------
__global__ void cvt_all_kernel(
    const float4* __restrict__ x,  float4* __restrict__ xt,
    const float4* __restrict__ a0, float4* __restrict__ o0,
    const float4* __restrict__ a1, float4* __restrict__ o1,
    const float4* __restrict__ a2, float4* __restrict__ o2,
    const float4* __restrict__ a3, float4* __restrict__ o3)
{
    const int NX = (B_ * L_ * D_) / 4;
    const int NW = (D_ * H_ * HD_) / 4;      // 2^20
    int i = blockIdx.x * blockDim.x + threadIdx.x;
    int stride = gridDim.x * blockDim.x;
    for (; i < NX + 4 * NW; i += stride) {
        const float4* src; float4* dst; int o;
        if (i < NX) { src = x; dst = xt; o = i; }
        else {
            int j = i - NX; int w = j >> 20; o = j & (NW - 1);
            switch (w) {
                case 0: src = a0; dst = o0; break;
                case 1: src = a1; dst = o1; break;
                case 2: src = a2; dst = o2; break;
                default: src = a3; dst = o3; break;
            }
        }
        float4 v = src[o];
        dst[o] = make_float4(rnd(v.x), rnd(v.y), rnd(v.z), rnd(v.w));
    }
}

// ---------------------------------------------------------------------------
// TF32 GEMM (round-8, verified): cp.async 3-stage, BK=32, 2 CTAs/SM.
// MODE 0: scatter fp32 to (B,H,L,hd). MODE 1: row-major fp32.
// MODE 2: scatter + tf32-round (for V).
// ---------------------------------------------------------------------------
#define AS_LD 36
#define BS_LD 136
#define ST_A (128 * AS_LD)
#define ST_B (32 * BS_LD)
#define ST_W (ST_A + ST_B)
#define GEMM_SMEM (3 * ST_W * 4)    // 107520 B

template <int MODE>
__global__ __launch_bounds__(256, 2) void gemm_tf32(
    const float* __restrict__ A, const float* __restrict__ Bm,
    float* __restrict__ C, int M, int N, int K)
{
    extern __shared__ unsigned smu[];

    const int tid  = threadIdx.x;
    const int warp = tid >> 5, lane = tid & 31;
    const int qr = lane >> 2, qc = lane & 3;
    const int wm = (warp & 1) * 64;
    const int wn = (warp >> 1) * 32;
    const int bm = blockIdx.y * 128, bn = blockIdx.x * 128;

    const int rA = tid >> 3, cA = (tid & 7) * 4;
    const int rB = tid >> 5, cB = (tid & 31) * 4;

    const float* Agl = A + (size_t)(bm + rA) * K + cA;
    const float* Bgl = Bm + (size_t)rB * N + bn + cB;

    float acc[4][4][4];
#pragma unroll
    for (int mt = 0; mt < 4; mt++)
#pragma unroll
        for (int nt = 0; nt < 4; nt++)
#pragma unroll
            for (int u = 0; u < 4; u++) acc[mt][nt][u] = 0.f;

    const int NCHUNK = K >> 5;

    auto issue = [&](int s, int k0) {
        unsigned* As = smu + s * ST_W;
        unsigned* Bs = As + ST_A;
#pragma unroll
        for (int it = 0; it < 4; it++)
            cp16(&As[(rA + it * 32) * AS_LD + cA], Agl + (size_t)(it * 32) * K + k0);
#pragma unroll
        for (int it = 0; it < 4; it++)
            cp16(&Bs[(rB + it * 8) * BS_LD + cB], Bgl + (size_t)(k0 + it * 8) * N);
        asm volatile("cp.async.commit_group;");
    };

    issue(0, 0);
    issue(1, 32);

    int cur = 0, pf = 2;
    for (int ch = 0; ch < NCHUNK; ch++) {
        asm volatile("cp.async.wait_group 1;");
        __syncthreads();

        if (ch + 2 < NCHUNK) {
            issue(pf, (ch + 2) << 5);
        } else {
            asm volatile("cp.async.commit_group;");
        }

        const unsigned* As = smu + cur * ST_W;
        const unsigned* Bs = As + ST_A;

#pragma unroll
        for (int s = 0; s < 4; s++) {
            const int kb = s * 8;
            unsigned a[4][4], b[4][2];
#pragma unroll
            for (int mt = 0; mt < 4; mt++) {
                int m = wm + mt * 16 + qr;
                a[mt][0] = As[m * AS_LD + kb + qc];
                a[mt][1] = As[(m + 8) * AS_LD + kb + qc];
                a[mt][2] = As[m * AS_LD + kb + qc + 4];
                a[mt][3] = As[(m + 8) * AS_LD + kb + qc + 4];
            }
#pragma unroll
            for (int nt = 0; nt < 4; nt++) {
                int n = wn + nt * 8 + qr;
                b[nt][0] = Bs[(kb + qc) * BS_LD + n];
                b[nt][1] = Bs[(kb + qc + 4) * BS_LD + n];
            }
#pragma unroll
            for (int mt = 0; mt < 4; mt++)
#pragma unroll
                for (int nt = 0; nt < 4; nt++)
                    mma_tf32(acc[mt][nt], a[mt], b[nt][0], b[nt][1]);
        }

        cur = (cur == 2) ? 0 : cur + 1;
        pf  = (pf  == 2) ? 0 : pf  + 1;
    }

#pragma unroll
    for (int mt = 0; mt < 4; mt++) {
#pragma unroll
        for (int nt = 0; nt < 4; nt++) {
            int row = bm + wm + mt * 16 + qr;
            int col = bn + wn + nt * 8 + 2 * qc;
            float2 r0, r1;
            if (MODE == 2) {
                r0 = make_float2(rnd(acc[mt][nt][0]), rnd(acc[mt][nt][1]));
                r1 = make_float2(rnd(acc[mt][nt][2]), rnd(acc[mt][nt][3]));
            } else {
                r0 = make_float2(acc[mt][nt][0], acc[mt][nt][1]);
                r1 = make_float2(acc[mt][nt][2], acc[mt][nt][3]);
            }
            if (MODE == 0 || MODE == 2) {
                int b0 = row >> 11, l0 = row & (L_ - 1);
                int h = col >> 7, d = col & (HD_ - 1);
                *(float2*)(C + ((((size_t)b0 * H_ + h) * L_ + l0) * HD_ + d)) = r0;
                int row1 = row + 8;
                int b1 = row1 >> 11, l1 = row1 & (L_ - 1);
                *(float2*)(C + ((((size_t)b1 * H_ + h) * L_ + l1) * HD_ + d)) = r1;
            } else {
                *(float2*)(C + (size_t)row * N + col) = r0;
                *(float2*)(C + (size_t)(row + 8) * N + col) = r1;
            }
        }
    }
}

// ---------------------------------------------------------------------------
// RoPE in-place; stores tf32-rounded results.
// ---------------------------------------------------------------------------
__global__ void rope_kernel(float* __restrict__ qb, float* __restrict__ kb)
{
    int idx = blockIdx.x * blockDim.x + threadIdx.x;
    if (idx >= B_ * H_ * L_ * 64) return;
    int j  = idx & 63;
    int l  = (idx >> 6) & (L_ - 1);
    int bh = idx >> 17;

    float freq = expf(-9.210340371976184f * (float)j * (1.0f / 64.0f));
    float ang = (float)l * freq;
    float s, c;
    sincosf(ang, &s, &c);

    size_t base = ((size_t)bh * L_ + l) * HD_ + j;
    float q1 = qb[base], q2 = qb[base + 64];
    qb[base]      = rnd(q1 * c - q2 * s);
    qb[base + 64] = rnd(q1 * s + q2 * c);
    float k1 = kb[base], k2 = kb[base + 64];
    kb[base]      = rnd(k1 * c - k2 * s);
    kb[base + 64] = rnd(k1 * s + k2 * c);
}

// ---------------------------------------------------------------------------
// Attention v3 (round-8 numerics, bit-identical):
//  - Q entirely in registers (a-fragment layout) — no Q smem, no a-frag LDS.
//  - K+V double-buffered via cp.async (one commit group per tile, 2 syncs).
//  - S and PV tf32 m16n8k8; P through smem (tf32-rounded).
// smem (words): K0@0[64x132] K1@8448 V0@16896[64x136] V1@25600 PS@34304[128x68]
// epilogue overlays: Ms[128][136]@0, Ns[128]@17408
// ---------------------------------------------------------------------------
#define K0_OFF 0
#define K1_OFF 8448
#define V0_OFF 16896
#define V1_OFF 25600
#define PS_OFF 34304
#define MS_OFF 0
#define NS_OFF 17408
#define LDK 132
#define LDV 136
#define LDP 68
#define LDM 136
#define ATTN_SMEM (43008 * 4)   // 172032 B

__global__ __launch_bounds__(256, 1) void attn_tc(
    const float* __restrict__ qb, const float* __restrict__ kb,
    const float* __restrict__ vb, const float* __restrict__ gatep,
    const float* __restrict__ memp, const float* __restrict__ normp,
    float* __restrict__ cb)
{
    extern __shared__ float smf[];
    unsigned* smu = (unsigned*)smf;

    const int tid = threadIdx.x;
    const int w = tid >> 5, lane = tid & 31;
    const int qr = lane >> 2, qc = lane & 3;
    const int qt = blockIdx.x;
    const int bh = blockIdx.y;
    const int h  = bh & (H_ - 1);
    const int b  = bh >> 4;
    const int m0 = w * 16 + qr;

    const float* qblk  = qb + ((size_t)bh * L_ + qt * 128) * HD_;
    const float* kbase = kb + (size_t)bh * L_ * HD_;
    const float* vbase = vb + (size_t)bh * L_ * HD_;

    // cp.async one (K,V) tile -> buffer kt&1
    auto issue_kv = [&](int kt) {
        unsigned kOff = (kt & 1) ? K1_OFF : K0_OFF;
        unsigned vOff = (kt & 1) ? V1_OFF : V0_OFF;
#pragma unroll
        for (int it = 0; it < 8; it++) {
            int item = tid + it * 256;
            int row = item >> 5, colf = (item & 31) * 4;
            cp16(&smu[kOff + row * LDK + colf],
                 kbase + (size_t)(kt * 64 + row) * HD_ + colf);
            cp16(&smu[vOff + row * LDV + colf],
                 vbase + (size_t)(kt * 64 + row) * HD_ + colf);
        }
        asm volatile("cp.async.commit_group;");
    };

    issue_kv(0);

    // Q a-fragments in registers: qa[ks] = {Q[m0][8ks+qc], Q[m0+8][8ks+qc],
    //                                       Q[m0][8ks+qc+4], Q[m0+8][8ks+qc+4]}
    unsigned qa[16][4];
#pragma unroll
    for (int ks = 0; ks < 16; ks++) {
        qa[ks][0] = __float_as_uint(qblk[(size_t)m0 * HD_ + 8 * ks + qc]);
        qa[ks][1] = __float_as_uint(qblk[(size_t)(m0 + 8) * HD_ + 8 * ks + qc]);
        qa[ks][2] = __float_as_uint(qblk[(size_t)m0 * HD_ + 8 * ks + qc + 4]);
        qa[ks][3] = __float_as_uint(qblk[(size_t)(m0 + 8) * HD_ + 8 * ks + qc + 4]);
    }

    float o[16][4];
#pragma unroll
    for (int nt = 0; nt < 16; nt++)
#pragma unroll
        for (int u = 0; u < 4; u++) o[nt][u] = 0.f;
    float mrow0 = -1e30f, mrow1 = -1e30f;
    float lrow0 = 0.f, lrow1 = 0.f;

    const float scale = 0.08838834764831845f;

    for (int kt = 0; kt < 32; kt++) {
        asm volatile("cp.async.wait_group 0;");
        __syncthreads();
        if (kt + 1 < 32) issue_kv(kt + 1);

        const unsigned* Kb = smu + ((kt & 1) ? K1_OFF : K0_OFF);
        const unsigned* Vb = smu + ((kt & 1) ? V1_OFF : V0_OFF);

        // ---- S = Q K^T (tf32, A from registers) ----
        float sa[8][4];
#pragma unroll
        for (int nt = 0; nt < 8; nt++)
#pragma unroll
            for (int u = 0; u < 4; u++) sa[nt][u] = 0.f;

#pragma unroll
        for (int ks = 0; ks < 16; ks++) {
            const int kb8 = ks * 8;
#pragma unroll
            for (int nt = 0; nt < 8; nt++) {
                int n = nt * 8 + qr;
                unsigned b0 = Kb[n * LDK + kb8 + qc];
                unsigned b1 = Kb[n * LDK + kb8 + qc + 4];
                mma_tf32(sa[nt], qa[ks], b0, b1);
            }
        }

        // ---- online softmax; P -> smem (tf32-rounded) ----
        float cand0 = -1e30f, cand1 = -1e30f;
#pragma unroll
        for (int nt = 0; nt < 8; nt++) {
            cand0 = fmaxf(cand0, fmaxf(sa[nt][0], sa[nt][1]));
            cand1 = fmaxf(cand1, fmaxf(sa[nt][2], sa[nt][3]));
        }
        cand0 *= scale; cand1 *= scale;
        cand0 = fmaxf(cand0, __shfl_xor_sync(0xffffffffu, cand0, 1));
        cand0 = fmaxf(cand0, __shfl_xor_sync(0xffffffffu, cand0, 2));
        cand1 = fmaxf(cand1, __shfl_xor_sync(0xffffffffu, cand1, 1));
        cand1 = fmaxf(cand1, __shfl_xor_sync(0xffffffffu, cand1, 2));

        float newm0 = fmaxf(mrow0, cand0), newm1 = fmaxf(mrow1, cand1);
        float corr0 = __expf(mrow0 - newm0), corr1 = __expf(mrow1 - newm1);
        mrow0 = newm0; mrow1 = newm1;

        float psum0 = 0.f, psum1 = 0.f;
#pragma unroll
        for (int nt = 0; nt < 8; nt++) {
            float p0 = __expf(sa[nt][0] * scale - newm0);
            float p1 = __expf(sa[nt][1] * scale - newm0);
            float p2 = __expf(sa[nt][2] * scale - newm1);
            float p3 = __expf(sa[nt][3] * scale - newm1);
            psum0 += p0 + p1; psum1 += p2 + p3;
            float2 lo, hi;
            lo.x = rnd(p0); lo.y = rnd(p1);
            hi.x = rnd(p2); hi.y = rnd(p3);
            *(float2*)&smf[PS_OFF + m0 * LDP + nt * 8 + 2 * qc] = lo;
            *(float2*)&smf[PS_OFF + (m0 + 8) * LDP + nt * 8 + 2 * qc] = hi;
        }
        psum0 += __shfl_xor_sync(0xffffffffu, psum0, 1);
        psum0 += __shfl_xor_sync(0xffffffffu, psum0, 2);
        psum1 += __shfl_xor_sync(0xffffffffu, psum1, 1);
        psum1 += __shfl_xor_sync(0xffffffffu, psum1, 2);
        lrow0 = lrow0 * corr0 + psum0;
        lrow1 = lrow1 * corr1 + psum1;

#pragma unroll
        for (int nt = 0; nt < 16; nt++) {
            o[nt][0] *= corr0; o[nt][1] *= corr0;
            o[nt][2] *= corr1; o[nt][3] *= corr1;
        }
        __syncthreads();   // P visible

        // ---- O += P V (tf32) ----
#pragma unroll
        for (int ks = 0; ks < 8; ks++) {
            const int kb8 = ks * 8;
            unsigned a[4];
            a[0] = __float_as_uint(smf[PS_OFF + m0 * LDP + kb8 + qc]);
            a[1] = __float_as_uint(smf[PS_OFF + (m0 + 8) * LDP + kb8 + qc]);
            a[2] = __float_as_uint(smf[PS_OFF + m0 * LDP + kb8 + qc + 4]);
            a[3] = __float_as_uint(smf[PS_OFF + (m0 + 8) * LDP + kb8 + qc + 4]);
#pragma unroll
            for (int nt = 0; nt < 16; nt++) {
                int n = nt * 8 + qr;
                unsigned b0 = Vb[(kb8 + qc) * LDV + n];
                unsigned b1 = Vb[(kb8 + qc + 4) * LDV + n];
                mma_tf32(o[nt], a, b0, b1);
            }
        }
    }

    // ================== epilogue: memory path ==================
    __syncthreads();   // all PV reads done before overlaying M/N

    const float* mptr = memp + (size_t)bh * HD_ * HD_;
#pragma unroll
    for (int it = 0; it < 16; it++) {
        int row = w + 8 * it;
        float4 v = *(const float4*)(mptr + (size_t)row * HD_ + lane * 4);
        *(uint4*)&smu[MS_OFF + row * LDM + lane * 4] =
            make_uint4(f2tf32(v.x), f2tf32(v.y), f2tf32(v.z), f2tf32(v.w));
    }
    if (tid < 128) smf[NS_OFF + tid] = normp[(size_t)bh * HD_ + tid];

    // q_f = elu(q)+1 on register Q (same elements, same rounding as round 8)
#pragma unroll
    for (int ks = 0; ks < 16; ks++)
#pragma unroll
        for (int u = 0; u < 4; u++) {
            float qv = __uint_as_float(qa[ks][u]);
            float qf = qv > 0.f ? qv + 1.f : __expf(qv);
            qa[ks][u] = f2tf32(qf);
        }
    __syncthreads();

    // denom: same d-order as round 8 (d = qc, qc+4, qc+8, ...)
    float den0 = 0.f, den1 = 0.f;
#pragma unroll
    for (int ks = 0; ks < 16; ks++) {
        float n0 = smf[NS_OFF + 8 * ks + qc];
        float n4 = smf[NS_OFF + 8 * ks + qc + 4];
        den0 = fmaf(__uint_as_float(qa[ks][0]), n0, den0);
        den0 = fmaf(__uint_as_float(qa[ks][2]), n4, den0);
        den1 = fmaf(__uint_as_float(qa[ks][1]), n0, den1);
        den1 = fmaf(__uint_as_float(qa[ks][3]), n4, den1);
    }
    den0 += __shfl_xor_sync(0xffffffffu, den0, 1);
    den0 += __shfl_xor_sync(0xffffffffu, den0, 2);
    den1 += __shfl_xor_sync(0xffffffffu, den1, 1);
    den1 += __shfl_xor_sync(0xffffffffu, den1, 2);

    const float g  = 1.f / (1.f + __expf(-gatep[h]));
    const float og = 1.f - g;
    const float invl0 = og / lrow0, invl1 = og / lrow1;
    const float invd0 = g / den0,   invd1 = g / den1;

    const int l0 = qt * 128 + m0;
    float* dst0 = cb + ((size_t)b * L_ + l0) * (H_ * HD_) + h * HD_;
    float* dst1 = cb + ((size_t)b * L_ + l0 + 8) * (H_ * HD_) + h * HD_;

#pragma unroll
    for (int pass = 0; pass < 2; pass++) {
        float ma[8][4];
#pragma unroll
        for (int nt = 0; nt < 8; nt++)
#pragma unroll
            for (int u = 0; u < 4; u++) ma[nt][u] = 0.f;

#pragma unroll
        for (int ks = 0; ks < 16; ks++) {
            const int kb8 = ks * 8;
#pragma unroll
            for (int nt = 0; nt < 8; nt++) {
                int n = (pass * 8 + nt) * 8 + qr;
                unsigned b0 = smu[MS_OFF + (kb8 + qc) * LDM + n];
                unsigned b1 = smu[MS_OFF + (kb8 + qc + 4) * LDM + n];
                mma_tf32(ma[nt], qa[ks], b0, b1);
            }
        }

#pragma unroll
        for (int nt = 0; nt < 8; nt++) {
            int gnt = pass * 8 + nt;
            int col = gnt * 8 + 2 * qc;
            float2 r0, r1;
            r0.x = rnd(ma[nt][0] * invd0 + o[gnt][0] * invl0);
            r0.y = rnd(ma[nt][1] * invd0 + o[gnt][1] * invl0);
            r1.x = rnd(ma[nt][2] * invd1 + o[gnt][2] * invl1);
            r1.y = rnd(ma[nt][3] * invd1 + o[gnt][3] * invl1);
            *(float2*)(dst0 + col) = r0;
            *(float2*)(dst1 + col) = r1;
        }
    }
}

// ---------------------------------------------------------------------------

extern "C" void kernel_launch(void* const* d_in, const int* in_sizes, int n_in,
                              void* d_out, int out_size)
{
    const float* x      = (const float*)d_in[0];
    const float* Wq     = (const float*)d_in[1];
    const float* Wk     = (const float*)d_in[2];
    const float* Wv     = (const float*)d_in[3];
    const float* Wo     = (const float*)d_in[4];
    const float* gate   = (const float*)d_in[5];
    const float* memory = (const float*)d_in[6];
    const float* norm   = (const float*)d_in[7];
    float* out = (float*)d_out;

    float *qb, *kb, *vb, *cb, *xt, *w0, *w1, *w2, *w3;
    cudaGetSymbolAddress((void**)&qb, g_q);
    cudaGetSymbolAddress((void**)&kb, g_k);
    cudaGetSymbolAddress((void**)&vb, g_v);
    cudaGetSymbolAddress((void**)&cb, g_c);
    cudaGetSymbolAddress((void**)&xt, g_xt);
    cudaGetSymbolAddress((void**)&w0, g_w0);
    cudaGetSymbolAddress((void**)&w1, g_w1);
    cudaGetSymbolAddress((void**)&w2, g_w2);
    cudaGetSymbolAddress((void**)&w3, g_w3);

    cvt_all_kernel<<<2048, 256>>>(
        (const float4*)x,  (float4*)xt,
        (const float4*)Wq, (float4*)w0,
        (const float4*)Wk, (float4*)w1,
        (const float4*)Wv, (float4*)w2,
        (const float4*)Wo, (float4*)w3);

    cudaFuncSetAttribute(gemm_tf32<0>, cudaFuncAttributeMaxDynamicSharedMemorySize, GEMM_SMEM);
    cudaFuncSetAttribute(gemm_tf32<1>, cudaFuncAttributeMaxDynamicSharedMemorySize, GEMM_SMEM);
    cudaFuncSetAttribute(gemm_tf32<2>, cudaFuncAttributeMaxDynamicSharedMemorySize, GEMM_SMEM);

    dim3 gg(16, 32);
    gemm_tf32<0><<<gg, 256, GEMM_SMEM>>>(xt, w0, qb, B_ * L_, H_ * HD_, D_);
    gemm_tf32<0><<<gg, 256, GEMM_SMEM>>>(xt, w1, kb, B_ * L_, H_ * HD_, D_);

    int nrope = B_ * H_ * L_ * 64;
    rope_kernel<<<nrope / 256, 256>>>(qb, kb);

    gemm_tf32<2><<<gg, 256, GEMM_SMEM>>>(xt, w2, vb, B_ * L_, H_ * HD_, D_);

    cudaFuncSetAttribute(attn_tc, cudaFuncAttributeMaxDynamicSharedMemorySize, ATTN_SMEM);
    attn_tc<<<dim3(16, 32), 256, ATTN_SMEM>>>(qb, kb, vb, gate, memory, norm, cb);  // ncu slot

    gemm_tf32<1><<<gg, 256, GEMM_SMEM>>>(cb, w3, out, B_ * L_, H_ * HD_, D_);
}

// round 11
// speedup vs baseline: 1.4237x; 1.0826x over previous
#include <cuda_runtime.h>
#include <math.h>

#define B_  2
#define L_  2048
#define D_  2048
#define H_  16
#define HD_ 128

// Scratch (static __device__ — no runtime allocation)
__device__ float g_q[(size_t)B_ * H_ * L_ * HD_];   // d-permuted within 8
__device__ float g_k[(size_t)B_ * H_ * L_ * HD_];   // d-permuted within 8
__device__ float g_v[(size_t)B_ * H_ * L_ * HD_];   // TRANSPOSED [bh][d][st(l)]
__device__ float g_c[(size_t)B_ * L_ * H_ * HD_];   // col-permuted within 8
__device__ float g_xt[(size_t)B_ * L_ * D_];        // col-permuted within 8
__device__ float g_w0[(size_t)D_ * H_ * HD_];
__device__ float g_w1[(size_t)D_ * H_ * HD_];
__device__ float g_w2[(size_t)D_ * H_ * HD_];
__device__ float g_w3[(size_t)D_ * H_ * HD_];

__device__ __forceinline__ unsigned f2tf32(float f) {
    unsigned u;
    asm("cvt.rna.tf32.f32 %0, %1;" : "=r"(u) : "f"(f));
    return u;
}
__device__ __forceinline__ float rnd(float f) { return __uint_as_float(f2tf32(f)); }

__device__ __forceinline__ void mma_tf32(float* c, const unsigned* a,
                                         unsigned b0, unsigned b1) {
    asm volatile(
        "mma.sync.aligned.m16n8k8.row.col.f32.tf32.tf32.f32 "
        "{%0,%1,%2,%3},{%4,%5,%6,%7},{%8,%9},{%0,%1,%2,%3};\n"
        : "+f"(c[0]), "+f"(c[1]), "+f"(c[2]), "+f"(c[3])
        : "r"(a[0]), "r"(a[1]), "r"(a[2]), "r"(a[3]), "r"(b0), "r"(b1));
}

__device__ __forceinline__ void cp16(void* smp, const void* g) {
    unsigned s = (unsigned)__cvta_generic_to_shared(smp);
    asm volatile("cp.async.cg.shared.global [%0], [%1], 16;" :: "r"(s), "l"(g));
}

// ---------------------------------------------------------------------------
// Fused tf32 pre-round. x is also column-permuted within each 8
// (positions hold cols 0,4,1,5,2,6,3,7) so GEMM a-frags are LDS.64.
// Weights rounded, natural layout.
// ---------------------------------------------------------------------------
__global__ void cvt_all_kernel(
    const float4* __restrict__ x,  float4* __restrict__ xt,
    const float4* __restrict__ a0, float4* __restrict__ o0,
    const float4* __restrict__ a1, float4* __restrict__ o1,
    const float4* __restrict__ a2, float4* __restrict__ o2,
    const float4* __restrict__ a3, float4* __restrict__ o3)
{
    const int GX = (B_ * L_ * D_) / 8;       // 8-col groups of x (2^20)
    const int NW = (D_ * H_ * HD_) / 4;      // float4s per weight (2^20)
    int i = blockIdx.x * blockDim.x + threadIdx.x;
    int stride = gridDim.x * blockDim.x;
    for (; i < GX + 4 * NW; i += stride) {
        if (i < GX) {
            float4 lo = x[2 * i], hi = x[2 * i + 1];
            xt[2 * i]     = make_float4(rnd(lo.x), rnd(hi.x), rnd(lo.y), rnd(hi.y));
            xt[2 * i + 1] = make_float4(rnd(lo.z), rnd(hi.z), rnd(lo.w), rnd(hi.w));
        } else {
            int j = i - GX; int w = j >> 20; int o = j & (NW - 1);
            const float4* src; float4* dst;
            switch (w) {
                case 0: src = a0; dst = o0; break;
                case 1: src = a1; dst = o1; break;
                case 2: src = a2; dst = o2; break;
                default: src = a3; dst = o3; break;
            }
            float4 v = src[o];
            dst[o] = make_float4(rnd(v.x), rnd(v.y), rnd(v.z), rnd(v.w));
        }
    }
}

// ---------------------------------------------------------------------------
// TF32 GEMM: cp.async 3-stage, BK=32, 2 CTAs/SM. A gmem is col-permuted ->
// a-fragments are single LDS.64 (AS_LD=40: (20*qr+qc)%16 distinct per phase).
// MODE 0: scatter q/k to (B,H,L,hd) with d-permutation (for attn .64 reads).
// MODE 1: natural row-major (final output).
// MODE 2: scatter V transposed [bh][d][st(l)] + tf32-round.
// ---------------------------------------------------------------------------
#define AS_LD 40
#define BS_LD 136
#define ST_A (128 * AS_LD)          // 5120 w
#define ST_B (32 * BS_LD)           // 4352 w
#define ST_W (ST_A + ST_B)          // 9472 w
#define GEMM_SMEM (3 * ST_W * 4)    // 113664 B

template <int MODE>
__global__ __launch_bounds__(256, 2) void gemm_tf32(
    const float* __restrict__ A, const float* __restrict__ Bm,
    float* __restrict__ C, int M, int N, int K)
{
    extern __shared__ unsigned smu[];

    const int tid  = threadIdx.x;
    const int warp = tid >> 5, lane = tid & 31;
    const int qr = lane >> 2, qc = lane & 3;
    const int wm = (warp & 1) * 64;
    const int wn = (warp >> 1) * 32;
    const int bm = blockIdx.y * 128, bn = blockIdx.x * 128;

    const int rA = tid >> 3, cA = (tid & 7) * 4;
    const int rB = tid >> 5, cB = (tid & 31) * 4;

    const float* Agl = A + (size_t)(bm + rA) * K + cA;
    const float* Bgl = Bm + (size_t)rB * N + bn + cB;

    float acc[4][4][4];
#pragma unroll
    for (int mt = 0; mt < 4; mt++)
#pragma unroll
        for (int nt = 0; nt < 4; nt++)
#pragma unroll
            for (int u = 0; u < 4; u++) acc[mt][nt][u] = 0.f;

    const int NCHUNK = K >> 5;

    auto issue = [&](int s, int k0) {
        unsigned* As = smu + s * ST_W;
        unsigned* Bs = As + ST_A;
#pragma unroll
        for (int it = 0; it < 4; it++)
            cp16(&As[(rA + it * 32) * AS_LD + cA], Agl + (size_t)(it * 32) * K + k0);
#pragma unroll
        for (int it = 0; it < 4; it++)
            cp16(&Bs[(rB + it * 8) * BS_LD + cB], Bgl + (size_t)(k0 + it * 8) * N);
        asm volatile("cp.async.commit_group;");
    };

    issue(0, 0);
    issue(1, 32);

    int cur = 0, pf = 2;
    for (int ch = 0; ch < NCHUNK; ch++) {
        asm volatile("cp.async.wait_group 1;");
        __syncthreads();

        if (ch + 2 < NCHUNK) {
            issue(pf, (ch + 2) << 5);
        } else {
            asm volatile("cp.async.commit_group;");
        }

        const unsigned* As = smu + cur * ST_W;
        const unsigned* Bs = As + ST_A;

#pragma unroll
        for (int s = 0; s < 4; s++) {
            const int kb = s * 8;
            unsigned a[4][4], b[4][2];
#pragma unroll
            for (int mt = 0; mt < 4; mt++) {
                int m = wm + mt * 16 + qr;
                uint2 t0 = *(const uint2*)&As[m * AS_LD + kb + 2 * qc];
                uint2 t1 = *(const uint2*)&As[(m + 8) * AS_LD + kb + 2 * qc];
                a[mt][0] = t0.x; a[mt][2] = t0.y;
                a[mt][1] = t1.x; a[mt][3] = t1.y;
            }
#pragma unroll
            for (int nt = 0; nt < 4; nt++) {
                int n = wn + nt * 8 + qr;
                b[nt][0] = Bs[(kb + qc) * BS_LD + n];
                b[nt][1] = Bs[(kb + qc + 4) * BS_LD + n];
            }
#pragma unroll
            for (int mt = 0; mt < 4; mt++)
#pragma unroll
                for (int nt = 0; nt < 4; nt++)
                    mma_tf32(acc[mt][nt], a[mt], b[nt][0], b[nt][1]);
        }

        cur = (cur == 2) ? 0 : cur + 1;
        pf  = (pf  == 2) ? 0 : pf  + 1;
    }

    // p8 = permuted position of col 2qc within its 8-group; col 2qc+1 -> p8+2
    const int p8 = (qc < 2) ? 4 * qc : 4 * (qc - 2) + 1;

#pragma unroll
    for (int mt = 0; mt < 4; mt++) {
#pragma unroll
        for (int nt = 0; nt < 4; nt++) {
            int row = bm + wm + mt * 16 + qr;
            int col = bn + wn + nt * 8 + 2 * qc;
            if (MODE == 0) {
                // q/k: d-permuted scatter
                int b0 = row >> 11, l0 = row & (L_ - 1);
                int h = col >> 7, d = col & (HD_ - 1);
                int dp = (d - 2 * qc) + p8;
                float* base0 = C + ((((size_t)b0 * H_ + h) * L_ + l0) * HD_);
                base0[dp]     = acc[mt][nt][0];
                base0[dp + 2] = acc[mt][nt][1];
                int l1 = l0 + 8;
                float* base1 = C + ((((size_t)b0 * H_ + h) * L_ + l1) * HD_);
                base1[dp]     = acc[mt][nt][2];
                base1[dp + 2] = acc[mt][nt][3];
            } else if (MODE == 2) {
                // V transposed: Vt[bh][d][st(l)]
                int b0 = row >> 11, l0 = row & (L_ - 1);
                int h = col >> 7, d = col & (HD_ - 1);
                int c7 = l0 & 7;
                int stl = (l0 & ~7) | (2 * (c7 & 3) + (c7 >> 2));
                size_t vb = (((size_t)(b0 * H_ + h)) * HD_ + d) * L_ + stl;
                C[vb]            = rnd(acc[mt][nt][0]);
                C[vb + L_]       = rnd(acc[mt][nt][1]);   // d+1
                C[vb + 8]        = rnd(acc[mt][nt][2]);   // l0+8
                C[vb + L_ + 8]   = rnd(acc[mt][nt][3]);
            } else {
                float2 r0 = make_float2(acc[mt][nt][0], acc[mt][nt][1]);
                float2 r1 = make_float2(acc[mt][nt][2], acc[mt][nt][3]);
                *(float2*)(C + (size_t)row * N + col) = r0;
                *(float2*)(C + (size_t)(row + 8) * N + col) = r1;
            }
        }
    }
}

// ---------------------------------------------------------------------------
// RoPE in-place on d-permuted q/k. Logical col j lives at (j&~7)|perm(j&7);
// j+64 at the same position +64 (64 is a multiple of 8).
// ---------------------------------------------------------------------------
__global__ void rope_kernel(float* __restrict__ qb, float* __restrict__ kb)
{
    int idx = blockIdx.x * blockDim.x + threadIdx.x;
    if (idx >= B_ * H_ * L_ * 64) return;
    int j  = idx & 63;
    int l  = (idx >> 6) & (L_ - 1);
    int bh = idx >> 17;

    float freq = expf(-9.210340371976184f * (float)j * (1.0f / 64.0f));
    float ang = (float)l * freq;
    float s, c;
    sincosf(ang, &s, &c);

    int c7 = j & 7;
    int jp = (j & ~7) | (2 * (c7 & 3) + (c7 >> 2));

    size_t base = ((size_t)bh * L_ + l) * HD_ + jp;
    float q1 = qb[base], q2 = qb[base + 64];
    qb[base]      = rnd(q1 * c - q2 * s);
    qb[base + 64] = rnd(q1 * s + q2 * c);
    float k1 = kb[base], k2 = kb[base + 64];
    kb[base]      = rnd(k1 * c - k2 * s);
    kb[base + 64] = rnd(k1 * s + k2 * c);
}

// ---------------------------------------------------------------------------
// Attention v4 (round-10 numerics, bit-identical):
//  - Q in registers (float2 loads from permuted gmem).
//  - K rows d-permuted  -> S-phase b-frags are LDS.64 (LDK=136).
//  - V transposed + key-permuted -> PV b-frags are LDS.64 (LDVt=72).
//  - cb written col-permuted (A of gemmO).
// smem (words): K0@0[64x136] K1@8704 V0@17408[128x72] V1@26624 PS@35840[128x68]
// epilogue overlays: Ms[128][136]@0, Ns[128]@35840
// ---------------------------------------------------------------------------
#define K0_OFF 0
#define K1_OFF 8704
#define V0_OFF 17408
#define V1_OFF 26624
#define PS_OFF 35840
#define MS_OFF 0
#define NS_OFF 35840
#define LDK 136
#define LDVT 72
#define LDP 68
#define LDM 136
#define ATTN_SMEM (44544 * 4)   // 178176 B

__global__ __launch_bounds__(256, 1) void attn_tc(
    const float* __restrict__ qb, const float* __restrict__ kb,
    const float* __restrict__ vb, const float* __restrict__ gatep,
    const float* __restrict__ memp, const float* __restrict__ normp,
    float* __restrict__ cb)
{
    extern __shared__ float smf[];
    unsigned* smu = (unsigned*)smf;

    const int tid = threadIdx.x;
    const int w = tid >> 5, lane = tid & 31;
    const int qr = lane >> 2, qc = lane & 3;
    const int qt = blockIdx.x;
    const int bh = blockIdx.y;
    const int h  = bh & (H_ - 1);
    const int b  = bh >> 4;
    const int m0 = w * 16 + qr;

    const float* qblk  = qb + ((size_t)bh * L_ + qt * 128) * HD_;
    const float* kbase = kb + (size_t)bh * L_ * HD_;
    const float* vbase = vb + (size_t)bh * HD_ * L_;   // transposed [d][st(l)]

    // cp.async one (K,Vt) tile -> buffer kt&1
    auto issue_kv = [&](int kt) {
        unsigned kOff = (kt & 1) ? K1_OFF : K0_OFF;
        unsigned vOff = (kt & 1) ? V1_OFF : V0_OFF;
#pragma unroll
        for (int it = 0; it < 8; it++) {
            int item = tid + it * 256;
            int row = item >> 5, colf = (item & 31) * 4;   // K: 64 rows x 32 chunks
            cp16(&smu[kOff + row * LDK + colf],
                 kbase + (size_t)(kt * 64 + row) * HD_ + colf);
        }
#pragma unroll
        for (int it = 0; it < 8; it++) {
            int item = tid + it * 256;
            int d = item >> 4, ch = (item & 15) * 4;       // Vt: 128 rows x 16 chunks
            cp16(&smu[vOff + d * LDVT + ch],
                 vbase + (size_t)d * L_ + kt * 64 + ch);
        }
        asm volatile("cp.async.commit_group;");
    };

    issue_kv(0);

    // Q a-fragments from permuted gmem: one float2 gives (col 8ks+qc, 8ks+qc+4)
    unsigned qa[16][4];
#pragma unroll
    for (int ks = 0; ks < 16; ks++) {
        uint2 t0 = *(const uint2*)&qblk[(size_t)m0 * HD_ + 8 * ks + 2 * qc];
        uint2 t1 = *(const uint2*)&qblk[(size_t)(m0 + 8) * HD_ + 8 * ks + 2 * qc];
        qa[ks][0] = t0.x; qa[ks][2] = t0.y;
        qa[ks][1] = t1.x; qa[ks][3] = t1.y;
    }

    float o[16][4];
#pragma unroll
    for (int nt = 0; nt < 16; nt++)
#pragma unroll
        for (int u = 0; u < 4; u++) o[nt][u] = 0.f;
    float mrow0 = -1e30f, mrow1 = -1e30f;
    float lrow0 = 0.f, lrow1 = 0.f;

    const float scale = 0.08838834764831845f;

    for (int kt = 0; kt < 32; kt++) {
        asm volatile("cp.async.wait_group 0;");
        __syncthreads();
        if (kt + 1 < 32) issue_kv(kt + 1);

        const unsigned* Kb = smu + ((kt & 1) ? K1_OFF : K0_OFF);
        const unsigned* Vb = smu + ((kt & 1) ? V1_OFF : V0_OFF);

        // ---- S = Q K^T (tf32, b-frags via LDS.64) ----
        float sa[8][4];
#pragma unroll
        for (int nt = 0; nt < 8; nt++)
#pragma unroll
            for (int u = 0; u < 4; u++) sa[nt][u] = 0.f;

#pragma unroll
        for (int ks = 0; ks < 16; ks++) {
            const int kb8 = ks * 8;
#pragma unroll
            for (int nt = 0; nt < 8; nt++) {
                int n = nt * 8 + qr;
                uint2 bb = *(const uint2*)&Kb[n * LDK + kb8 + 2 * qc];
                mma_tf32(sa[nt], qa[ks], bb.x, bb.y);
            }
        }

        // ---- online softmax; P -> smem (tf32-rounded) ----
        float cand0 = -1e30f, cand1 = -1e30f;
#pragma unroll
        for (int nt = 0; nt < 8; nt++) {
            cand0 = fmaxf(cand0, fmaxf(sa[nt][0], sa[nt][1]));
            cand1 = fmaxf(cand1, fmaxf(sa[nt][2], sa[nt][3]));
        }
        cand0 *= scale; cand1 *= scale;
        cand0 = fmaxf(cand0, __shfl_xor_sync(0xffffffffu, cand0, 1));
        cand0 = fmaxf(cand0, __shfl_xor_sync(0xffffffffu, cand0, 2));
        cand1 = fmaxf(cand1, __shfl_xor_sync(0xffffffffu, cand1, 1));
        cand1 = fmaxf(cand1, __shfl_xor_sync(0xffffffffu, cand1, 2));

        float newm0 = fmaxf(mrow0, cand0), newm1 = fmaxf(mrow1, cand1);
        float corr0 = __expf(mrow0 - newm0), corr1 = __expf(mrow1 - newm1);
        mrow0 = newm0; mrow1 = newm1;

        float psum0 = 0.f, psum1 = 0.f;
#pragma unroll
        for (int nt = 0; nt < 8; nt++) {
            float p0 = __expf(sa[nt][0] * scale - newm0);
            float p1 = __expf(sa[nt][1] * scale - newm0);
            float p2 = __expf(sa[nt][2] * scale - newm1);
            float p3 = __expf(sa[nt][3] * scale - newm1);
            psum0 += p0 + p1; psum1 += p2 + p3;
            float2 lo, hi;
            lo.x = rnd(p0); lo.y = rnd(p1);
            hi.x = rnd(p2); hi.y = rnd(p3);
            *(float2*)&smf[PS_OFF + m0 * LDP + nt * 8 + 2 * qc] = lo;
            *(float2*)&smf[PS_OFF + (m0 + 8) * LDP + nt * 8 + 2 * qc] = hi;
        }
        psum0 += __shfl_xor_sync(0xffffffffu, psum0, 1);
        psum0 += __shfl_xor_sync(0xffffffffu, psum0, 2);
        psum1 += __shfl_xor_sync(0xffffffffu, psum1, 1);
        psum1 += __shfl_xor_sync(0xffffffffu, psum1, 2);
        lrow0 = lrow0 * corr0 + psum0;
        lrow1 = lrow1 * corr1 + psum1;

#pragma unroll
        for (int nt = 0; nt < 16; nt++) {
            o[nt][0] *= corr0; o[nt][1] *= corr0;
            o[nt][2] *= corr1; o[nt][3] *= corr1;
        }
        __syncthreads();   // P visible

        // ---- O += P V (tf32, Vt b-frags via LDS.64) ----
#pragma unroll
        for (int ks = 0; ks < 8; ks++) {
            const int kb8 = ks * 8;
            unsigned a[4];
            a[0] = __float_as_uint(smf[PS_OFF + m0 * LDP + kb8 + qc]);
            a[1] = __float_as_uint(smf[PS_OFF + (m0 + 8) * LDP + kb8 + qc]);
            a[2] = __float_as_uint(smf[PS_OFF + m0 * LDP + kb8 + qc + 4]);
            a[3] = __float_as_uint(smf[PS_OFF + (m0 + 8) * LDP + kb8 + qc + 4]);
#pragma unroll
            for (int nt = 0; nt < 16; nt++) {
                int n = nt * 8 + qr;
                uint2 bb = *(const uint2*)&Vb[n * LDVT + kb8 + 2 * qc];
                mma_tf32(o[nt], a, bb.x, bb.y);
            }
        }
    }

    // ================== epilogue: memory path ==================
    __syncthreads();   // all PV reads done before overlaying M/N

    const float* mptr = memp + (size_t)bh * HD_ * HD_;
#pragma unroll
    for (int it = 0; it < 16; it++) {
        int row = w + 8 * it;
        float4 v = *(const float4*)(mptr + (size_t)row * HD_ + lane * 4);
        *(uint4*)&smu[MS_OFF + row * LDM + lane * 4] =
            make_uint4(f2tf32(v.x), f2tf32(v.y), f2tf32(v.z), f2tf32(v.w));
    }
    if (tid < 128) smf[NS_OFF + tid] = normp[(size_t)bh * HD_ + tid];

    // q_f = elu(q)+1 on register Q (same elements/rounding as round 10)
#pragma unroll
    for (int ks = 0; ks < 16; ks++)
#pragma unroll
        for (int u = 0; u < 4; u++) {
            float qv = __uint_as_float(qa[ks][u]);
            float qf = qv > 0.f ? qv + 1.f : __expf(qv);
            qa[ks][u] = f2tf32(qf);
        }
    __syncthreads();

    // denom: identical order to round 10
    float den0 = 0.f, den1 = 0.f;
#pragma unroll
    for (int ks = 0; ks < 16; ks++) {
        float n0 = smf[NS_OFF + 8 * ks + qc];
        float n4 = smf[NS_OFF + 8 * ks + qc + 4];
        den0 = fmaf(__uint_as_float(qa[ks][0]), n0, den0);
        den0 = fmaf(__uint_as_float(qa[ks][2]), n4, den0);
        den1 = fmaf(__uint_as_float(qa[ks][1]), n0, den1);
        den1 = fmaf(__uint_as_float(qa[ks][3]), n4, den1);
    }
    den0 += __shfl_xor_sync(0xffffffffu, den0, 1);
    den0 += __shfl_xor_sync(0xffffffffu, den0, 2);
    den1 += __shfl_xor_sync(0xffffffffu, den1, 1);
    den1 += __shfl_xor_sync(0xffffffffu, den1, 2);

    const float g  = 1.f / (1.f + __expf(-gatep[h]));
    const float og = 1.f - g;
    const float invl0 = og / lrow0, invl1 = og / lrow1;
    const float invd0 = g / den0,   invd1 = g / den1;

    const int l0 = qt * 128 + m0;
    float* dst0 = cb + ((size_t)b * L_ + l0) * (H_ * HD_) + h * HD_;
    float* dst1 = cb + ((size_t)b * L_ + l0 + 8) * (H_ * HD_) + h * HD_;

    // permuted position for col 2qc within its 8-group (cb is gemmO's A)
    const int p8 = (qc < 2) ? 4 * qc : 4 * (qc - 2) + 1;

#pragma unroll
    for (int pass = 0; pass < 2; pass++) {
        float ma[8][4];
#pragma unroll
        for (int nt = 0; nt < 8; nt++)
#pragma unroll
            for (int u = 0; u < 4; u++) ma[nt][u] = 0.f;

#pragma unroll
        for (int ks = 0; ks < 16; ks++) {
            const int kb8 = ks * 8;
#pragma unroll
            for (int nt = 0; nt < 8; nt++) {
                int n = (pass * 8 + nt) * 8 + qr;
                unsigned b0 = smu[MS_OFF + (kb8 + qc) * LDM + n];
                unsigned b1 = smu[MS_OFF + (kb8 + qc + 4) * LDM + n];
                mma_tf32(ma[nt], qa[ks], b0, b1);
            }
        }

#pragma unroll
        for (int nt = 0; nt < 8; nt++) {
            int gnt = pass * 8 + nt;
            int grp = gnt * 8;                 // col group base (col = grp + 2qc)
            float r00 = rnd(ma[nt][0] * invd0 + o[gnt][0] * invl0);
            float r01 = rnd(ma[nt][1] * invd0 + o[gnt][1] * invl0);
            float r10 = rnd(ma[nt][2] * invd1 + o[gnt][2] * invl1);
            float r11 = rnd(ma[nt][3] * invd1 + o[gnt][3] * invl1);
            dst0[grp + p8]     = r00;
            dst0[grp + p8 + 2] = r01;
            dst1[grp + p8]     = r10;
            dst1[grp + p8 + 2] = r11;
        }
    }
}

// ---------------------------------------------------------------------------

extern "C" void kernel_launch(void* const* d_in, const int* in_sizes, int n_in,
                              void* d_out, int out_size)
{
    const float* x      = (const float*)d_in[0];
    const float* Wq     = (const float*)d_in[1];
    const float* Wk     = (const float*)d_in[2];
    const float* Wv     = (const float*)d_in[3];
    const float* Wo     = (const float*)d_in[4];
    const float* gate   = (const float*)d_in[5];
    const float* memory = (const float*)d_in[6];
    const float* norm   = (const float*)d_in[7];
    float* out = (float*)d_out;

    float *qb, *kb, *vb, *cb, *xt, *w0, *w1, *w2, *w3;
    cudaGetSymbolAddress((void**)&qb, g_q);
    cudaGetSymbolAddress((void**)&kb, g_k);
    cudaGetSymbolAddress((void**)&vb, g_v);
    cudaGetSymbolAddress((void**)&cb, g_c);
    cudaGetSymbolAddress((void**)&xt, g_xt);
    cudaGetSymbolAddress((void**)&w0, g_w0);
    cudaGetSymbolAddress((void**)&w1, g_w1);
    cudaGetSymbolAddress((void**)&w2, g_w2);
    cudaGetSymbolAddress((void**)&w3, g_w3);

    cvt_all_kernel<<<2048, 256>>>(
        (const float4*)x,  (float4*)xt,
        (const float4*)Wq, (float4*)w0,
        (const float4*)Wk, (float4*)w1,
        (const float4*)Wv, (float4*)w2,
        (const float4*)Wo, (float4*)w3);

    cudaFuncSetAttribute(gemm_tf32<0>, cudaFuncAttributeMaxDynamicSharedMemorySize, GEMM_SMEM);
    cudaFuncSetAttribute(gemm_tf32<1>, cudaFuncAttributeMaxDynamicSharedMemorySize, GEMM_SMEM);
    cudaFuncSetAttribute(gemm_tf32<2>, cudaFuncAttributeMaxDynamicSharedMemorySize, GEMM_SMEM);

    dim3 gg(16, 32);
    gemm_tf32<0><<<gg, 256, GEMM_SMEM>>>(xt, w0, qb, B_ * L_, H_ * HD_, D_);
    gemm_tf32<0><<<gg, 256, GEMM_SMEM>>>(xt, w1, kb, B_ * L_, H_ * HD_, D_);

    int nrope = B_ * H_ * L_ * 64;
    rope_kernel<<<nrope / 256, 256>>>(qb, kb);

    gemm_tf32<2><<<gg, 256, GEMM_SMEM>>>(xt, w2, vb, B_ * L_, H_ * HD_, D_);

    cudaFuncSetAttribute(attn_tc, cudaFuncAttributeMaxDynamicSharedMemorySize, ATTN_SMEM);
    attn_tc<<<dim3(16, 32), 256, ATTN_SMEM>>>(qb, kb, vb, gate, memory, norm, cb);

    gemm_tf32<1><<<gg, 256, GEMM_SMEM>>>(cb, w3, out, B_ * L_, H_ * HD_, D_);
}

// round 12
// speedup vs baseline: 1.5058x; 1.0577x over previous
#include <cuda_runtime.h>
#include <math.h>

#define B_  2
#define L_  2048
#define D_  2048
#define H_  16
#define HD_ 128

// Scratch (static __device__ — no runtime allocation)
__device__ float g_q[(size_t)B_ * H_ * L_ * HD_];   // d-permuted within 8
__device__ float g_k[(size_t)B_ * H_ * L_ * HD_];   // d-permuted within 8
__device__ float g_v[(size_t)B_ * H_ * L_ * HD_];   // TRANSPOSED [bh][d][st(l)]
__device__ float g_c[(size_t)B_ * L_ * H_ * HD_];   // col-permuted within 8
__device__ float g_xt[(size_t)B_ * L_ * D_];        // col-permuted within 8
__device__ float g_w0[(size_t)D_ * H_ * HD_];
__device__ float g_w1[(size_t)D_ * H_ * HD_];
__device__ float g_w2[(size_t)D_ * H_ * HD_];
__device__ float g_w3[(size_t)D_ * H_ * HD_];

__device__ __forceinline__ unsigned f2tf32(float f) {
    unsigned u;
    asm("cvt.rna.tf32.f32 %0, %1;" : "=r"(u) : "f"(f));
    return u;
}
__device__ __forceinline__ float rnd(float f) { return __uint_as_float(f2tf32(f)); }

__device__ __forceinline__ void mma_tf32(float* c, const unsigned* a,
                                         unsigned b0, unsigned b1) {
    asm volatile(
        "mma.sync.aligned.m16n8k8.row.col.f32.tf32.tf32.f32 "
        "{%0,%1,%2,%3},{%4,%5,%6,%7},{%8,%9},{%0,%1,%2,%3};\n"
        : "+f"(c[0]), "+f"(c[1]), "+f"(c[2]), "+f"(c[3])
        : "r"(a[0]), "r"(a[1]), "r"(a[2]), "r"(a[3]), "r"(b0), "r"(b1));
}

__device__ __forceinline__ void cp16(void* smp, const void* g) {
    unsigned s = (unsigned)__cvta_generic_to_shared(smp);
    asm volatile("cp.async.cg.shared.global [%0], [%1], 16;" :: "r"(s), "l"(g));
}

// ---------------------------------------------------------------------------
// Fused tf32 pre-round. x column-permuted within each 8 (0,4,1,5,2,6,3,7);
// weights rounded, natural layout.
// ---------------------------------------------------------------------------
__global__ void cvt_all_kernel(
    const float4* __restrict__ x,  float4* __restrict__ xt,
    const float4* __restrict__ a0, float4* __restrict__ o0,
    const float4* __restrict__ a1, float4* __restrict__ o1,
    const float4* __restrict__ a2, float4* __restrict__ o2,
    const float4* __restrict__ a3, float4* __restrict__ o3)
{
    const int GX = (B_ * L_ * D_) / 8;       // 2^20
    const int NW = (D_ * H_ * HD_) / 4;      // 2^20
    int i = blockIdx.x * blockDim.x + threadIdx.x;
    int stride = gridDim.x * blockDim.x;
    for (; i < GX + 4 * NW; i += stride) {
        if (i < GX) {
            float4 lo = x[2 * i], hi = x[2 * i + 1];
            xt[2 * i]     = make_float4(rnd(lo.x), rnd(hi.x), rnd(lo.y), rnd(hi.y));
            xt[2 * i + 1] = make_float4(rnd(lo.z), rnd(hi.z), rnd(lo.w), rnd(hi.w));
        } else {
            int j = i - GX; int w = j >> 20; int o = j & (NW - 1);
            const float4* src; float4* dst;
            switch (w) {
                case 0: src = a0; dst = o0; break;
                case 1: src = a1; dst = o1; break;
                case 2: src = a2; dst = o2; break;
                default: src = a3; dst = o3; break;
            }
            float4 v = src[o];
            dst[o] = make_float4(rnd(v.x), rnd(v.y), rnd(v.z), rnd(v.w));
        }
    }
}

// ---------------------------------------------------------------------------
// GEMM mainloop constants (shared by qkv-merged kernel and gemmO).
// ---------------------------------------------------------------------------
#define AS_LD 40
#define BS_LD 136
#define ST_A (128 * AS_LD)
#define ST_B (32 * BS_LD)
#define ST_W (ST_A + ST_B)
#define GEMM_SMEM (3 * ST_W * 4)    // 113664 B

// ---------------------------------------------------------------------------
// Merged Q/K/V projection GEMM: grid (16, 32, 3); blockIdx.z selects
// (weight, destination, epilogue mode). Identical math per block to R11.
//   z=0: w0 -> qb  (d-permuted scatter)
//   z=1: w1 -> kb  (d-permuted scatter)
//   z=2: w2 -> vb  (transposed + key-permuted scatter, tf32-rounded)
// ---------------------------------------------------------------------------
__global__ __launch_bounds__(256, 2) void gemm_qkv(
    const float* __restrict__ A,
    const float* __restrict__ W0, const float* __restrict__ W1,
    const float* __restrict__ W2,
    float* __restrict__ qb, float* __restrict__ kb, float* __restrict__ vb)
{
    extern __shared__ unsigned smu[];

    const int K = D_, N = H_ * HD_;
    const int bz = blockIdx.z;
    const float* Bm = (bz == 0) ? W0 : (bz == 1) ? W1 : W2;
    float* C = (bz == 0) ? qb : (bz == 1) ? kb : vb;

    const int tid  = threadIdx.x;
    const int warp = tid >> 5, lane = tid & 31;
    const int qr = lane >> 2, qc = lane & 3;
    const int wm = (warp & 1) * 64;
    const int wn = (warp >> 1) * 32;
    const int bm = blockIdx.y * 128, bn = blockIdx.x * 128;

    const int rA = tid >> 3, cA = (tid & 7) * 4;
    const int rB = tid >> 5, cB = (tid & 31) * 4;

    const float* Agl = A + (size_t)(bm + rA) * K + cA;
    const float* Bgl = Bm + (size_t)rB * N + bn + cB;

    float acc[4][4][4];
#pragma unroll
    for (int mt = 0; mt < 4; mt++)
#pragma unroll
        for (int nt = 0; nt < 4; nt++)
#pragma unroll
            for (int u = 0; u < 4; u++) acc[mt][nt][u] = 0.f;

    const int NCHUNK = K >> 5;

    auto issue = [&](int s, int k0) {
        unsigned* As = smu + s * ST_W;
        unsigned* Bs = As + ST_A;
#pragma unroll
        for (int it = 0; it < 4; it++)
            cp16(&As[(rA + it * 32) * AS_LD + cA], Agl + (size_t)(it * 32) * K + k0);
#pragma unroll
        for (int it = 0; it < 4; it++)
            cp16(&Bs[(rB + it * 8) * BS_LD + cB], Bgl + (size_t)(k0 + it * 8) * N);
        asm volatile("cp.async.commit_group;");
    };

    issue(0, 0);
    issue(1, 32);

    int cur = 0, pf = 2;
    for (int ch = 0; ch < NCHUNK; ch++) {
        asm volatile("cp.async.wait_group 1;");
        __syncthreads();

        if (ch + 2 < NCHUNK) {
            issue(pf, (ch + 2) << 5);
        } else {
            asm volatile("cp.async.commit_group;");
        }

        const unsigned* As = smu + cur * ST_W;
        const unsigned* Bs = As + ST_A;

#pragma unroll
        for (int s = 0; s < 4; s++) {
            const int kb8 = s * 8;
            unsigned a[4][4], b[4][2];
#pragma unroll
            for (int mt = 0; mt < 4; mt++) {
                int m = wm + mt * 16 + qr;
                uint2 t0 = *(const uint2*)&As[m * AS_LD + kb8 + 2 * qc];
                uint2 t1 = *(const uint2*)&As[(m + 8) * AS_LD + kb8 + 2 * qc];
                a[mt][0] = t0.x; a[mt][2] = t0.y;
                a[mt][1] = t1.x; a[mt][3] = t1.y;
            }
#pragma unroll
            for (int nt = 0; nt < 4; nt++) {
                int n = wn + nt * 8 + qr;
                b[nt][0] = Bs[(kb8 + qc) * BS_LD + n];
                b[nt][1] = Bs[(kb8 + qc + 4) * BS_LD + n];
            }
#pragma unroll
            for (int mt = 0; mt < 4; mt++)
#pragma unroll
                for (int nt = 0; nt < 4; nt++)
                    mma_tf32(acc[mt][nt], a[mt], b[nt][0], b[nt][1]);
        }

        cur = (cur == 2) ? 0 : cur + 1;
        pf  = (pf  == 2) ? 0 : pf  + 1;
    }

    const int p8 = (qc < 2) ? 4 * qc : 4 * (qc - 2) + 1;

#pragma unroll
    for (int mt = 0; mt < 4; mt++) {
#pragma unroll
        for (int nt = 0; nt < 4; nt++) {
            int row = bm + wm + mt * 16 + qr;
            int col = bn + wn + nt * 8 + 2 * qc;
            if (bz != 2) {
                // q/k: d-permuted scatter
                int b0 = row >> 11, l0 = row & (L_ - 1);
                int h = col >> 7, d = col & (HD_ - 1);
                int dp = (d - 2 * qc) + p8;
                float* base0 = C + ((((size_t)b0 * H_ + h) * L_ + l0) * HD_);
                base0[dp]     = acc[mt][nt][0];
                base0[dp + 2] = acc[mt][nt][1];
                int l1 = l0 + 8;
                float* base1 = C + ((((size_t)b0 * H_ + h) * L_ + l1) * HD_);
                base1[dp]     = acc[mt][nt][2];
                base1[dp + 2] = acc[mt][nt][3];
            } else {
                // V transposed: Vt[bh][d][st(l)], tf32-rounded
                int b0 = row >> 11, l0 = row & (L_ - 1);
                int h = col >> 7, d = col & (HD_ - 1);
                int c7 = l0 & 7;
                int stl = (l0 & ~7) | (2 * (c7 & 3) + (c7 >> 2));
                size_t vb2 = (((size_t)(b0 * H_ + h)) * HD_ + d) * L_ + stl;
                C[vb2]          = rnd(acc[mt][nt][0]);
                C[vb2 + L_]     = rnd(acc[mt][nt][1]);
                C[vb2 + 8]      = rnd(acc[mt][nt][2]);
                C[vb2 + L_ + 8] = rnd(acc[mt][nt][3]);
            }
        }
    }
}

// ---------------------------------------------------------------------------
// Output GEMM (MODE 1 of R11, unchanged): natural row-major out.
// ---------------------------------------------------------------------------
__global__ __launch_bounds__(256, 2) void gemm_out(
    const float* __restrict__ A, const float* __restrict__ Bm,
    float* __restrict__ C, int M, int N, int K)
{
    extern __shared__ unsigned smu[];

    const int tid  = threadIdx.x;
    const int warp = tid >> 5, lane = tid & 31;
    const int qr = lane >> 2, qc = lane & 3;
    const int wm = (warp & 1) * 64;
    const int wn = (warp >> 1) * 32;
    const int bm = blockIdx.y * 128, bn = blockIdx.x * 128;

    const int rA = tid >> 3, cA = (tid & 7) * 4;
    const int rB = tid >> 5, cB = (tid & 31) * 4;

    const float* Agl = A + (size_t)(bm + rA) * K + cA;
    const float* Bgl = Bm + (size_t)rB * N + bn + cB;

    float acc[4][4][4];
#pragma unroll
    for (int mt = 0; mt < 4; mt++)
#pragma unroll
        for (int nt = 0; nt < 4; nt++)
#pragma unroll
            for (int u = 0; u < 4; u++) acc[mt][nt][u] = 0.f;

    const int NCHUNK = K >> 5;

    auto issue = [&](int s, int k0) {
        unsigned* As = smu + s * ST_W;
        unsigned* Bs = As + ST_A;
#pragma unroll
        for (int it = 0; it < 4; it++)
            cp16(&As[(rA + it * 32) * AS_LD + cA], Agl + (size_t)(it * 32) * K + k0);
#pragma unroll
        for (int it = 0; it < 4; it++)
            cp16(&Bs[(rB + it * 8) * BS_LD + cB], Bgl + (size_t)(k0 + it * 8) * N);
        asm volatile("cp.async.commit_group;");
    };

    issue(0, 0);
    issue(1, 32);

    int cur = 0, pf = 2;
    for (int ch = 0; ch < NCHUNK; ch++) {
        asm volatile("cp.async.wait_group 1;");
        __syncthreads();

        if (ch + 2 < NCHUNK) {
            issue(pf, (ch + 2) << 5);
        } else {
            asm volatile("cp.async.commit_group;");
        }

        const unsigned* As = smu + cur * ST_W;
        const unsigned* Bs = As + ST_A;

#pragma unroll
        for (int s = 0; s < 4; s++) {
            const int kb8 = s * 8;
            unsigned a[4][4], b[4][2];
#pragma unroll
            for (int mt = 0; mt < 4; mt++) {
                int m = wm + mt * 16 + qr;
                uint2 t0 = *(const uint2*)&As[m * AS_LD + kb8 + 2 * qc];
                uint2 t1 = *(const uint2*)&As[(m + 8) * AS_LD + kb8 + 2 * qc];
                a[mt][0] = t0.x; a[mt][2] = t0.y;
                a[mt][1] = t1.x; a[mt][3] = t1.y;
            }
#pragma unroll
            for (int nt = 0; nt < 4; nt++) {
                int n = wn + nt * 8 + qr;
                b[nt][0] = Bs[(kb8 + qc) * BS_LD + n];
                b[nt][1] = Bs[(kb8 + qc + 4) * BS_LD + n];
            }
#pragma unroll
            for (int mt = 0; mt < 4; mt++)
#pragma unroll
                for (int nt = 0; nt < 4; nt++)
                    mma_tf32(acc[mt][nt], a[mt], b[nt][0], b[nt][1]);
        }

        cur = (cur == 2) ? 0 : cur + 1;
        pf  = (pf  == 2) ? 0 : pf  + 1;
    }

#pragma unroll
    for (int mt = 0; mt < 4; mt++) {
#pragma unroll
        for (int nt = 0; nt < 4; nt++) {
            int row = bm + wm + mt * 16 + qr;
            int col = bn + wn + nt * 8 + 2 * qc;
            float2 r0 = make_float2(acc[mt][nt][0], acc[mt][nt][1]);
            float2 r1 = make_float2(acc[mt][nt][2], acc[mt][nt][3]);
            *(float2*)(C + (size_t)row * N + col) = r0;
            *(float2*)(C + (size_t)(row + 8) * N + col) = r1;
        }
    }
}

// ---------------------------------------------------------------------------
// RoPE in-place on d-permuted q/k (unchanged).
// ---------------------------------------------------------------------------
__global__ void rope_kernel(float* __restrict__ qb, float* __restrict__ kb)
{
    int idx = blockIdx.x * blockDim.x + threadIdx.x;
    if (idx >= B_ * H_ * L_ * 64) return;
    int j  = idx & 63;
    int l  = (idx >> 6) & (L_ - 1);
    int bh = idx >> 17;

    float freq = expf(-9.210340371976184f * (float)j * (1.0f / 64.0f));
    float ang = (float)l * freq;
    float s, c;
    sincosf(ang, &s, &c);

    int c7 = j & 7;
    int jp = (j & ~7) | (2 * (c7 & 3) + (c7 >> 2));

    size_t base = ((size_t)bh * L_ + l) * HD_ + jp;
    float q1 = qb[base], q2 = qb[base + 64];
    qb[base]      = rnd(q1 * c - q2 * s);
    qb[base + 64] = rnd(q1 * s + q2 * c);
    float k1 = kb[base], k2 = kb[base + 64];
    kb[base]      = rnd(k1 * c - k2 * s);
    kb[base + 64] = rnd(k1 * s + k2 * c);
}

// ---------------------------------------------------------------------------
// Attention (R11 numerics, bit-identical). ONE change: the per-tile
// "P visible" barrier is warp-local dataflow (P rows [w*16, w*16+16) are
// written and read by the same warp) -> __syncwarp() instead of
// __syncthreads(). The buffer-reuse barrier at loop top remains block-wide.
// ---------------------------------------------------------------------------
#define K0_OFF 0
#define K1_OFF 8704
#define V0_OFF 17408
#define V1_OFF 26624
#define PS_OFF 35840
#define MS_OFF 0
#define NS_OFF 35840
#define LDK 136
#define LDVT 72
#define LDP 68
#define LDM 136
#define ATTN_SMEM (44544 * 4)   // 178176 B

__global__ __launch_bounds__(256, 1) void attn_tc(
    const float* __restrict__ qb, const float* __restrict__ kb,
    const float* __restrict__ vb, const float* __restrict__ gatep,
    const float* __restrict__ memp, const float* __restrict__ normp,
    float* __restrict__ cb)
{
    extern __shared__ float smf[];
    unsigned* smu = (unsigned*)smf;

    const int tid = threadIdx.x;
    const int w = tid >> 5, lane = tid & 31;
    const int qr = lane >> 2, qc = lane & 3;
    const int qt = blockIdx.x;
    const int bh = blockIdx.y;
    const int h  = bh & (H_ - 1);
    const int b  = bh >> 4;
    const int m0 = w * 16 + qr;

    const float* qblk  = qb + ((size_t)bh * L_ + qt * 128) * HD_;
    const float* kbase = kb + (size_t)bh * L_ * HD_;
    const float* vbase = vb + (size_t)bh * HD_ * L_;

    auto issue_kv = [&](int kt) {
        unsigned kOff = (kt & 1) ? K1_OFF : K0_OFF;
        unsigned vOff = (kt & 1) ? V1_OFF : V0_OFF;
#pragma unroll
        for (int it = 0; it < 8; it++) {
            int item = tid + it * 256;
            int row = item >> 5, colf = (item & 31) * 4;
            cp16(&smu[kOff + row * LDK + colf],
                 kbase + (size_t)(kt * 64 + row) * HD_ + colf);
        }
#pragma unroll
        for (int it = 0; it < 8; it++) {
            int item = tid + it * 256;
            int d = item >> 4, ch = (item & 15) * 4;
            cp16(&smu[vOff + d * LDVT + ch],
                 vbase + (size_t)d * L_ + kt * 64 + ch);
        }
        asm volatile("cp.async.commit_group;");
    };

    issue_kv(0);

    unsigned qa[16][4];
#pragma unroll
    for (int ks = 0; ks < 16; ks++) {
        uint2 t0 = *(const uint2*)&qblk[(size_t)m0 * HD_ + 8 * ks + 2 * qc];
        uint2 t1 = *(const uint2*)&qblk[(size_t)(m0 + 8) * HD_ + 8 * ks + 2 * qc];
        qa[ks][0] = t0.x; qa[ks][2] = t0.y;
        qa[ks][1] = t1.x; qa[ks][3] = t1.y;
    }

    float o[16][4];
#pragma unroll
    for (int nt = 0; nt < 16; nt++)
#pragma unroll
        for (int u = 0; u < 4; u++) o[nt][u] = 0.f;
    float mrow0 = -1e30f, mrow1 = -1e30f;
    float lrow0 = 0.f, lrow1 = 0.f;

    const float scale = 0.08838834764831845f;

    for (int kt = 0; kt < 32; kt++) {
        asm volatile("cp.async.wait_group 0;");
        __syncthreads();
        if (kt + 1 < 32) issue_kv(kt + 1);

        const unsigned* Kb = smu + ((kt & 1) ? K1_OFF : K0_OFF);
        const unsigned* Vb = smu + ((kt & 1) ? V1_OFF : V0_OFF);

        float sa[8][4];
#pragma unroll
        for (int nt = 0; nt < 8; nt++)
#pragma unroll
            for (int u = 0; u < 4; u++) sa[nt][u] = 0.f;

#pragma unroll
        for (int ks = 0; ks < 16; ks++) {
            const int kb8 = ks * 8;
#pragma unroll
            for (int nt = 0; nt < 8; nt++) {
                int n = nt * 8 + qr;
                uint2 bb = *(const uint2*)&Kb[n * LDK + kb8 + 2 * qc];
                mma_tf32(sa[nt], qa[ks], bb.x, bb.y);
            }
        }

        float cand0 = -1e30f, cand1 = -1e30f;
#pragma unroll
        for (int nt = 0; nt < 8; nt++) {
            cand0 = fmaxf(cand0, fmaxf(sa[nt][0], sa[nt][1]));
            cand1 = fmaxf(cand1, fmaxf(sa[nt][2], sa[nt][3]));
        }
        cand0 *= scale; cand1 *= scale;
        cand0 = fmaxf(cand0, __shfl_xor_sync(0xffffffffu, cand0, 1));
        cand0 = fmaxf(cand0, __shfl_xor_sync(0xffffffffu, cand0, 2));
        cand1 = fmaxf(cand1, __shfl_xor_sync(0xffffffffu, cand1, 1));
        cand1 = fmaxf(cand1, __shfl_xor_sync(0xffffffffu, cand1, 2));

        float newm0 = fmaxf(mrow0, cand0), newm1 = fmaxf(mrow1, cand1);
        float corr0 = __expf(mrow0 - newm0), corr1 = __expf(mrow1 - newm1);
        mrow0 = newm0; mrow1 = newm1;

        float psum0 = 0.f, psum1 = 0.f;
#pragma unroll
        for (int nt = 0; nt < 8; nt++) {
            float p0 = __expf(sa[nt][0] * scale - newm0);
            float p1 = __expf(sa[nt][1] * scale - newm0);
            float p2 = __expf(sa[nt][2] * scale - newm1);
            float p3 = __expf(sa[nt][3] * scale - newm1);
            psum0 += p0 + p1; psum1 += p2 + p3;
            float2 lo, hi;
            lo.x = rnd(p0); lo.y = rnd(p1);
            hi.x = rnd(p2); hi.y = rnd(p3);
            *(float2*)&smf[PS_OFF + m0 * LDP + nt * 8 + 2 * qc] = lo;
            *(float2*)&smf[PS_OFF + (m0 + 8) * LDP + nt * 8 + 2 * qc] = hi;
        }
        psum0 += __shfl_xor_sync(0xffffffffu, psum0, 1);
        psum0 += __shfl_xor_sync(0xffffffffu, psum0, 2);
        psum1 += __shfl_xor_sync(0xffffffffu, psum1, 1);
        psum1 += __shfl_xor_sync(0xffffffffu, psum1, 2);
        lrow0 = lrow0 * corr0 + psum0;
        lrow1 = lrow1 * corr1 + psum1;

#pragma unroll
        for (int nt = 0; nt < 16; nt++) {
            o[nt][0] *= corr0; o[nt][1] *= corr0;
            o[nt][2] *= corr1; o[nt][3] *= corr1;
        }
        __syncwarp();   // P rows are warp-local: warp-level ordering suffices

#pragma unroll
        for (int ks = 0; ks < 8; ks++) {
            const int kb8 = ks * 8;
            unsigned a[4];
            a[0] = __float_as_uint(smf[PS_OFF + m0 * LDP + kb8 + qc]);
            a[1] = __float_as_uint(smf[PS_OFF + (m0 + 8) * LDP + kb8 + qc]);
            a[2] = __float_as_uint(smf[PS_OFF + m0 * LDP + kb8 + qc + 4]);
            a[3] = __float_as_uint(smf[PS_OFF + (m0 + 8) * LDP + kb8 + qc + 4]);
#pragma unroll
            for (int nt = 0; nt < 16; nt++) {
                int n = nt * 8 + qr;
                uint2 bb = *(const uint2*)&Vb[n * LDVT + kb8 + 2 * qc];
                mma_tf32(o[nt], a, bb.x, bb.y);
            }
        }
    }

    // ================== epilogue: memory path ==================
    __syncthreads();

    const float* mptr = memp + (size_t)bh * HD_ * HD_;
#pragma unroll
    for (int it = 0; it < 16; it++) {
        int row = w + 8 * it;
        float4 v = *(const float4*)(mptr + (size_t)row * HD_ + lane * 4);
        *(uint4*)&smu[MS_OFF + row * LDM + lane * 4] =
            make_uint4(f2tf32(v.x), f2tf32(v.y), f2tf32(v.z), f2tf32(v.w));
    }
    if (tid < 128) smf[NS_OFF + tid] = normp[(size_t)bh * HD_ + tid];

#pragma unroll
    for (int ks = 0; ks < 16; ks++)
#pragma unroll
        for (int u = 0; u < 4; u++) {
            float qv = __uint_as_float(qa[ks][u]);
            float qf = qv > 0.f ? qv + 1.f : __expf(qv);
            qa[ks][u] = f2tf32(qf);
        }
    __syncthreads();

    float den0 = 0.f, den1 = 0.f;
#pragma unroll
    for (int ks = 0; ks < 16; ks++) {
        float n0 = smf[NS_OFF + 8 * ks + qc];
        float n4 = smf[NS_OFF + 8 * ks + qc + 4];
        den0 = fmaf(__uint_as_float(qa[ks][0]), n0, den0);
        den0 = fmaf(__uint_as_float(qa[ks][2]), n4, den0);
        den1 = fmaf(__uint_as_float(qa[ks][1]), n0, den1);
        den1 = fmaf(__uint_as_float(qa[ks][3]), n4, den1);
    }
    den0 += __shfl_xor_sync(0xffffffffu, den0, 1);
    den0 += __shfl_xor_sync(0xffffffffu, den0, 2);
    den1 += __shfl_xor_sync(0xffffffffu, den1, 1);
    den1 += __shfl_xor_sync(0xffffffffu, den1, 2);

    const float g  = 1.f / (1.f + __expf(-gatep[h]));
    const float og = 1.f - g;
    const float invl0 = og / lrow0, invl1 = og / lrow1;
    const float invd0 = g / den0,   invd1 = g / den1;

    const int l0 = qt * 128 + m0;
    float* dst0 = cb + ((size_t)b * L_ + l0) * (H_ * HD_) + h * HD_;
    float* dst1 = cb + ((size_t)b * L_ + l0 + 8) * (H_ * HD_) + h * HD_;

    const int p8 = (qc < 2) ? 4 * qc : 4 * (qc - 2) + 1;

#pragma unroll
    for (int pass = 0; pass < 2; pass++) {
        float ma[8][4];
#pragma unroll
        for (int nt = 0; nt < 8; nt++)
#pragma unroll
            for (int u = 0; u < 4; u++) ma[nt][u] = 0.f;

#pragma unroll
        for (int ks = 0; ks < 16; ks++) {
            const int kb8 = ks * 8;
#pragma unroll
            for (int nt = 0; nt < 8; nt++) {
                int n = (pass * 8 + nt) * 8 + qr;
                unsigned b0 = smu[MS_OFF + (kb8 + qc) * LDM + n];
                unsigned b1 = smu[MS_OFF + (kb8 + qc + 4) * LDM + n];
                mma_tf32(ma[nt], qa[ks], b0, b1);
            }
        }

#pragma unroll
        for (int nt = 0; nt < 8; nt++) {
            int gnt = pass * 8 + nt;
            int grp = gnt * 8;
            float r00 = rnd(ma[nt][0] * invd0 + o[gnt][0] * invl0);
            float r01 = rnd(ma[nt][1] * invd0 + o[gnt][1] * invl0);
            float r10 = rnd(ma[nt][2] * invd1 + o[gnt][2] * invl1);
            float r11 = rnd(ma[nt][3] * invd1 + o[gnt][3] * invl1);
            dst0[grp + p8]     = r00;
            dst0[grp + p8 + 2] = r01;
            dst1[grp + p8]     = r10;
            dst1[grp + p8 + 2] = r11;
        }
    }
}

// ---------------------------------------------------------------------------

extern "C" void kernel_launch(void* const* d_in, const int* in_sizes, int n_in,
                              void* d_out, int out_size)
{
    const float* x      = (const float*)d_in[0];
    const float* Wq     = (const float*)d_in[1];
    const float* Wk     = (const float*)d_in[2];
    const float* Wv     = (const float*)d_in[3];
    const float* Wo     = (const float*)d_in[4];
    const float* gate   = (const float*)d_in[5];
    const float* memory = (const float*)d_in[6];
    const float* norm   = (const float*)d_in[7];
    float* out = (float*)d_out;

    float *qb, *kb, *vb, *cb, *xt, *w0, *w1, *w2, *w3;
    cudaGetSymbolAddress((void**)&qb, g_q);
    cudaGetSymbolAddress((void**)&kb, g_k);
    cudaGetSymbolAddress((void**)&vb, g_v);
    cudaGetSymbolAddress((void**)&cb, g_c);
    cudaGetSymbolAddress((void**)&xt, g_xt);
    cudaGetSymbolAddress((void**)&w0, g_w0);
    cudaGetSymbolAddress((void**)&w1, g_w1);
    cudaGetSymbolAddress((void**)&w2, g_w2);
    cudaGetSymbolAddress((void**)&w3, g_w3);

    // launch 0: fused tf32 pre-rounding
    cvt_all_kernel<<<2048, 256>>>(
        (const float4*)x,  (float4*)xt,
        (const float4*)Wq, (float4*)w0,
        (const float4*)Wk, (float4*)w1,
        (const float4*)Wv, (float4*)w2,
        (const float4*)Wo, (float4*)w3);

    cudaFuncSetAttribute(gemm_qkv, cudaFuncAttributeMaxDynamicSharedMemorySize, GEMM_SMEM);
    cudaFuncSetAttribute(gemm_out, cudaFuncAttributeMaxDynamicSharedMemorySize, GEMM_SMEM);

    // launch 1: merged Q/K/V projections (z selects weight/dst/mode)
    gemm_qkv<<<dim3(16, 32, 3), 256, GEMM_SMEM>>>(xt, w0, w1, w2, qb, kb, vb);

    // launch 2: rope
    int nrope = B_ * H_ * L_ * 64;
    rope_kernel<<<nrope / 256, 256>>>(qb, kb);

    // launch 3: attention  (ncu capture slot = 4th launch)
    cudaFuncSetAttribute(attn_tc, cudaFuncAttributeMaxDynamicSharedMemorySize, ATTN_SMEM);
    attn_tc<<<dim3(16, 32), 256, ATTN_SMEM>>>(qb, kb, vb, gate, memory, norm, cb);

    // launch 4: output projection
    gemm_out<<<dim3(16, 32), 256, GEMM_SMEM>>>(cb, w3, out, B_ * L_, H_ * HD_, D_);
}